// round 9
// baseline (speedup 1.0000x reference)
#include <cuda_runtime.h>
#include <cuda_fp16.h>
#include <cstdint>

// ============================================================================
// QATLinear: y[t,o] = scale[o] * sum_i x[t,i]*sign(w[o,i]) + b[o]
//
// R9: B as packed sign bits with CONSUMER-side expansion, SOFTWARE-PIPELINED:
// fragment jp+1 is expanded (SHF/LOP3) while fragment jp's two MMAs issue,
// so the ALU chain never directly stalls an MMA (R4's failure mode).
// Cuts B smem traffic 64KB->~0 and L2 feed 16.5GB->8.9GB while keeping the
// R7 skeleton: BM=BN=128, BK=64, 8 warps (32x64 tile), 2 CTAs/SM, single
// barrier per chunk, wave-parity phase stagger. STAGES=5 (A 16KB + bits 1KB).
// ============================================================================

#define TOKENS 8192
#define DIN    4096
#define DOUT   16384

static constexpr int BM = 128;
static constexpr int BN = 128;
static constexpr int BK = 64;
static constexpr int STAGES = 5;
static constexpr int THREADS = 256;              // 8 warps: 4 (m) x 2 (n)
static constexpr int NCHUNK = DIN / BK;          // 64
static constexpr int KWORDS = DIN / 32;          // 128

static constexpr int A_STAGE_B = BM * BK * 2;    // 16384 B
static constexpr int BITS_B    = BN * 2 * 4;     // 1024 B (2 kwords x 128 n)
static constexpr int STAGE_B   = A_STAGE_B + BITS_B;      // 17408
static constexpr int SMEM_TOTAL = STAGES * STAGE_B;       // 87040 per CTA

// ---- scratch (device globals: allocation-free rule) ----
__device__ __half    g_A [(size_t)TOKENS * DIN];          // 64 MB (x fp16)
__device__ uint32_t  g_Bb[(size_t)KWORDS * DOUT];         // 8 MB (sign bits)
// g_Bb[kw * DOUT + n] bit j = (w[n][kw*32+j] < 0)

// ============================ PTX helpers ===================================
__device__ __forceinline__ uint32_t smem_u32(const void* p) {
    uint32_t a;
    asm("{ .reg .u64 t; cvta.to.shared.u64 t, %1; cvt.u32.u64 %0, t; }"
        : "=r"(a) : "l"(p));
    return a;
}
__device__ __forceinline__ void cp_async16(uint32_t saddr, const void* gptr) {
    asm volatile("cp.async.cg.shared.global [%0], [%1], 16;"
                 :: "r"(saddr), "l"(gptr) : "memory");
}
__device__ __forceinline__ void cp_commit() {
    asm volatile("cp.async.commit_group;" ::: "memory");
}
template <int N>
__device__ __forceinline__ void cp_wait() {
    asm volatile("cp.async.wait_group %0;" :: "n"(N) : "memory");
}
__device__ __forceinline__ void ldmatrix_x4(uint32_t& r0, uint32_t& r1,
                                            uint32_t& r2, uint32_t& r3,
                                            uint32_t addr) {
    asm volatile("ldmatrix.sync.aligned.m8n8.x4.shared.b16 {%0,%1,%2,%3}, [%4];"
                 : "=r"(r0), "=r"(r1), "=r"(r2), "=r"(r3) : "r"(addr));
}
__device__ __forceinline__ uint32_t lds32(uint32_t addr) {
    uint32_t v;
    asm volatile("ld.shared.b32 %0, [%1];" : "=r"(v) : "r"(addr));
    return v;
}
__device__ __forceinline__ void mma_16816(float* c, const uint32_t* a,
                                          const uint32_t* b) {
    asm volatile(
        "mma.sync.aligned.m16n8k16.row.col.f32.f16.f16.f32 "
        "{%0,%1,%2,%3}, {%4,%5,%6,%7}, {%8,%9}, {%0,%1,%2,%3};"
        : "+f"(c[0]), "+f"(c[1]), "+f"(c[2]), "+f"(c[3])
        : "r"(a[0]), "r"(a[1]), "r"(a[2]), "r"(a[3]), "r"(b[0]), "r"(b[1]));
}
// A tile rows: 64 fp16 = 128 B = 8 x 16B chunks; chunk' = chunk ^ (row&7)
__device__ __forceinline__ uint32_t sw_off(int row, int chunk) {
    return (uint32_t)((row << 7) + ((chunk ^ (row & 7)) << 4));
}
// expand 2 sign-bit pairs -> fp16 +-1 b-fragment regs
__device__ __forceinline__ void expand_b(uint32_t t, uint32_t* b) {
    b[0] = 0x3C003C00u | ((t & 1u) << 15) | ((t & 2u) << 30);
    uint32_t t8 = t >> 8;
    b[1] = 0x3C003C00u | ((t8 & 1u) << 15) | ((t8 & 2u) << 30);
}

// ============================ prep kernels ==================================
__global__ void prep_a_kernel(const float* __restrict__ x) {
    size_t i = (size_t)blockIdx.x * blockDim.x + threadIdx.x;
    const size_t n4 = (size_t)TOKENS * DIN / 4;
    if (i >= n4) return;
    float4 v = __ldg((const float4*)x + i);
    uint32_t h0 = __half_as_ushort(__float2half_rn(v.x))
                | ((uint32_t)__half_as_ushort(__float2half_rn(v.y)) << 16);
    uint32_t h1 = __half_as_ushort(__float2half_rn(v.z))
                | ((uint32_t)__half_as_ushort(__float2half_rn(v.w)) << 16);
    uint2 p; p.x = h0; p.y = h1;
    ((uint2*)g_A)[i] = p;
}
// ballot-pack sign bits; bit=1 <=> w<0 (0,-0 -> +1 like reference)
__global__ void prep_b_kernel(const float* __restrict__ w) {
    size_t g = (size_t)blockIdx.x * blockDim.x + threadIdx.x;  // over DOUT*DIN
    float v = __ldg(w + g);
    uint32_t word = __ballot_sync(0xFFFFFFFFu, v < 0.0f);
    if ((threadIdx.x & 31) == 0) {
        size_t n  = g / DIN;
        size_t kw = (g % DIN) >> 5;
        g_Bb[kw * DOUT + n] = word;
    }
}

// ============================ GEMM kernel ===================================
__global__ void __launch_bounds__(THREADS, 2)
qat_gemm_kernel(const float* __restrict__ scale, const float* __restrict__ bias,
                float* __restrict__ out) {
    extern __shared__ char smem[];
    const uint32_t sbase = smem_u32(smem);
    const int tid  = threadIdx.x;
    const int wid  = tid >> 5;
    const int lane = tid & 31;

    // grouped tile swizzle (GROUP_M = 8): 64 m-tiles x 128 n-tiles
    const int pid   = blockIdx.x;                 // 0 .. 8191
    const int group = pid >> 10;
    const int inb   = pid & 1023;
    const int pid_m = (group << 3) + (inb & 7);
    const int pid_n = inb >> 3;
    const int m0 = pid_m * BM;
    const int n0 = pid_n * BN;

    // phase stagger: wave partners anti-align k-loops (R7 win, kept)
    const int coff = ((pid / 148) & 1) ? (NCHUNK / 2) : 0;

    // warp tile: 32 (m) x 64 (n); warps: 4 (m) x 2 (n)
    const int warp_m = wid & 3;
    const int warp_n = wid >> 2;
    const int wm0 = warp_m * 32;
    const int wn0 = warp_n * 64;

    // ---- A global load indices (16B per cp.async; rows are 8x16B chunks) ---
    const int g_row = tid >> 3;               // 0..31
    const int g_chk = tid & 7;
    const __half* gA0 = g_A + (size_t)(m0 + g_row) * DIN + g_chk * 8;
    const __half* gA1 = gA0 + (size_t)32 * DIN;
    const __half* gA2 = gA0 + (size_t)64 * DIN;
    const __half* gA3 = gA0 + (size_t)96 * DIN;
    const uint32_t sO0 = sw_off(g_row,      g_chk);
    const uint32_t sO1 = sw_off(g_row + 32, g_chk);
    const uint32_t sO2 = sw_off(g_row + 64, g_chk);
    const uint32_t sO3 = sw_off(g_row + 96, g_chk);

    // cc = pipeline position (slot = cc % STAGES); gmem chunk = rotated
    auto issue_stage = [&](int cc) {
        const int s = cc % STAGES;
        const int c = (cc + coff) & (NCHUNK - 1);
        const uint32_t stA = sbase + s * STAGE_B;
        const size_t kofs = (size_t)c * BK;
        cp_async16(stA + sO0, gA0 + kofs);
        cp_async16(stA + sO1, gA1 + kofs);
        cp_async16(stA + sO2, gA2 + kofs);
        cp_async16(stA + sO3, gA3 + kofs);
        if (tid < 64) {
            // bits: 2 kwords x 128 n = 1KB; kw = tid>>5, 4 n-words per thread
            const int kw = tid >> 5, nq = tid & 31;
            cp_async16(stA + A_STAGE_B + (kw << 9) + nq * 16,
                       g_Bb + (size_t)(2 * c + kw) * DOUT + n0 + nq * 4);
        }
    };

    // ---- prologue: fill STAGES-1 stages ----
#pragma unroll
    for (int cc = 0; cc < STAGES - 1; ++cc) { issue_stage(cc); cp_commit(); }

    // ---- accumulators: 2 m-frags x 8 n-frags x 4 ----
    float acc[2][8][4];
#pragma unroll
    for (int i = 0; i < 2; ++i)
#pragma unroll
        for (int j = 0; j < 8; ++j)
#pragma unroll
            for (int q = 0; q < 4; ++q) acc[i][j][q] = 0.0f;

    const int lquad = lane >> 3;
    const int lrow  = lane & 7;
    // bit-word smem offset for this lane's n-row (jp stride = 32B)
    const uint32_t wb_lane = (uint32_t)((wn0 + (lane >> 2)) << 2);
    const int q2 = (lane & 3) << 1;           // 2*(lane%4)

#pragma unroll 1
    for (int cc = 0; cc < NCHUNK; ++cc) {
        cp_wait<STAGES - 2>();
        __syncthreads();   // all warps done reading slot cc-1

        if (cc + STAGES - 1 < NCHUNK) { issue_stage(cc + STAGES - 1); cp_commit(); }

        const uint32_t stA  = sbase + (cc % STAGES) * STAGE_B;
        const uint32_t stBw = stA + A_STAGE_B;

        uint32_t wb[8];
#pragma unroll
        for (int kh = 0; kh < 4; ++kh) {      // four k16 halves of BK=64
            const int kchunk = kh * 2;

            // reload 8 bit-words when crossing into a new kword (kh=0,2)
            if ((kh & 1) == 0) {
                const uint32_t base = stBw + ((kh >> 1) << 9) + wb_lane;
#pragma unroll
                for (int jp = 0; jp < 8; ++jp) wb[jp] = lds32(base + (jp << 5));
            }
            const int sh = ((kh & 1) << 4) + q2;

            // A frags: 2 m16 tiles
            uint32_t afr[2][4];
#pragma unroll
            for (int mi = 0; mi < 2; ++mi) {
                int row = wm0 + mi * 16 + lrow + ((lquad & 1) << 3);
                int chk = kchunk + (lquad >> 1);
                ldmatrix_x4(afr[mi][0], afr[mi][1], afr[mi][2], afr[mi][3],
                            stA + sw_off(row, chk));
            }

            // software-pipelined b expansion: expand jp+1 during jp's MMAs
            uint32_t bc[2], bn[2];
            expand_b(wb[0] >> sh, bc);
#pragma unroll
            for (int jp = 0; jp < 8; ++jp) {
                if (jp < 7) expand_b(wb[jp + 1] >> sh, bn);
                mma_16816(acc[0][jp], afr[0], bc);
                mma_16816(acc[1][jp], afr[1], bc);
                bc[0] = bn[0]; bc[1] = bn[1];
            }
        }
    }

    // ---- epilogue: fused scale/bias, float2 stores ----
    const int tq = lane >> 2;
    const int tr = lane & 3;
#pragma unroll
    for (int j = 0; j < 8; ++j) {
        const int n = n0 + wn0 + j * 8 + 2 * tr;
        const float2 sc = *(const float2*)(scale + n);
        const float2 bb = *(const float2*)(bias + n);
#pragma unroll
        for (int mi = 0; mi < 2; ++mi) {
            const int mrow = m0 + wm0 + mi * 16 + tq;
            float2 v0, v1;
            v0.x = fmaf(sc.x, acc[mi][j][0], bb.x);
            v0.y = fmaf(sc.y, acc[mi][j][1], bb.y);
            v1.x = fmaf(sc.x, acc[mi][j][2], bb.x);
            v1.y = fmaf(sc.y, acc[mi][j][3], bb.y);
            *(float2*)(out + (size_t)mrow * DOUT + n) = v0;
            *(float2*)(out + (size_t)(mrow + 8) * DOUT + n) = v1;
        }
    }
}

// ============================ launch ========================================
extern "C" void kernel_launch(void* const* d_in, const int* in_sizes, int n_in,
                              void* d_out, int out_size) {
    (void)in_sizes; (void)n_in; (void)out_size;
    const float* x     = (const float*)d_in[0];
    const float* w     = (const float*)d_in[1];
    const float* scale = (const float*)d_in[2];
    const float* b     = (const float*)d_in[3];
    float* out = (float*)d_out;

    {
        size_t n4 = (size_t)TOKENS * DIN / 4;
        prep_a_kernel<<<(unsigned)((n4 + 255) / 256), 256>>>(x);
    }
    {
        size_t nt = (size_t)DOUT * DIN;
        prep_b_kernel<<<(unsigned)((nt + 255) / 256), 256>>>(w);
    }

    cudaFuncSetAttribute(qat_gemm_kernel,
                         cudaFuncAttributeMaxDynamicSharedMemorySize,
                         SMEM_TOTAL);
    const int grid = (TOKENS / BM) * (DOUT / BN);   // 8192
    qat_gemm_kernel<<<grid, THREADS, SMEM_TOTAL>>>(scale, b, out);
}

// round 10
// speedup vs baseline: 1.2417x; 1.2417x over previous
#include <cuda_runtime.h>
#include <cuda_fp16.h>
#include <cstdint>

// ============================================================================
// QATLinear: y[t,o] = scale[o] * sum_i x[t,i]*sign(w[o,i]) + b[o]
//
// sign(W)=+-1 exact in fp16; x as fp16, fp32 mma.sync accumulation.
// R10: PERSISTENT CTAs (grid=296=2x148) with a flat chunk-slot pipeline that
// crosses tile boundaries: prefetch for tile t+1 is in flight while tile t's
// last chunks compute and its epilogue stores -> per-tile drain/refill and
// epilogue exposure overlap away. MMA stream identical to R7 (the validated
// 85%-of-floor config): BM=BN=128, BK=64, 8 warps (32x64 tile), STAGES=3,
// 2 CTAs/SM, one barrier per chunk, per-CTA k-phase rotation.
// ============================================================================

#define TOKENS 8192
#define DIN    4096
#define DOUT   16384

static constexpr int BM = 128;
static constexpr int BN = 128;
static constexpr int BK = 64;
static constexpr int STAGES = 3;
static constexpr int THREADS = 256;              // 8 warps: 4 (m) x 2 (n)
static constexpr int NCHUNK = DIN / BK;          // 64
static constexpr int GRIDSZ = 296;               // 2 CTAs x 148 SMs
static constexpr int TOTAL_TILES = (TOKENS / BM) * (DOUT / BN);   // 8192

static constexpr int A_STAGE_B = BM * BK * 2;    // 16384 B
static constexpr int B_STAGE_B = BN * BK * 2;    // 16384 B
static constexpr int STAGE_B   = A_STAGE_B + B_STAGE_B;   // 32768
static constexpr int SMEM_TOTAL = STAGES * STAGE_B;       // 98304 per CTA

// ---- scratch (device globals: allocation-free rule) ----
__device__ __half g_A [(size_t)TOKENS * DIN];    // 64 MB  (x as fp16)
__device__ __half g_Bs[(size_t)DOUT  * DIN];     // 128 MB (sign(w) as fp16)

// ============================ PTX helpers ===================================
__device__ __forceinline__ uint32_t smem_u32(const void* p) {
    uint32_t a;
    asm("{ .reg .u64 t; cvta.to.shared.u64 t, %1; cvt.u32.u64 %0, t; }"
        : "=r"(a) : "l"(p));
    return a;
}
__device__ __forceinline__ void cp_async16(uint32_t saddr, const void* gptr) {
    asm volatile("cp.async.cg.shared.global [%0], [%1], 16;"
                 :: "r"(saddr), "l"(gptr) : "memory");
}
__device__ __forceinline__ void cp_commit() {
    asm volatile("cp.async.commit_group;" ::: "memory");
}
template <int N>
__device__ __forceinline__ void cp_wait() {
    asm volatile("cp.async.wait_group %0;" :: "n"(N) : "memory");
}
__device__ __forceinline__ void ldmatrix_x4(uint32_t& r0, uint32_t& r1,
                                            uint32_t& r2, uint32_t& r3,
                                            uint32_t addr) {
    asm volatile("ldmatrix.sync.aligned.m8n8.x4.shared.b16 {%0,%1,%2,%3}, [%4];"
                 : "=r"(r0), "=r"(r1), "=r"(r2), "=r"(r3) : "r"(addr));
}
__device__ __forceinline__ void mma_16816(float* c, const uint32_t* a,
                                          const uint32_t* b) {
    asm volatile(
        "mma.sync.aligned.m16n8k16.row.col.f32.f16.f16.f32 "
        "{%0,%1,%2,%3}, {%4,%5,%6,%7}, {%8,%9}, {%0,%1,%2,%3};"
        : "+f"(c[0]), "+f"(c[1]), "+f"(c[2]), "+f"(c[3])
        : "r"(a[0]), "r"(a[1]), "r"(a[2]), "r"(a[3]), "r"(b[0]), "r"(b[1]));
}
// tile rows: 64 fp16 = 128 B = 8 x 16B chunks; chunk' = chunk ^ (row&7)
__device__ __forceinline__ uint32_t sw_off(int row, int chunk) {
    return (uint32_t)((row << 7) + ((chunk ^ (row & 7)) << 4));
}

// ============================ prep kernels ==================================
__global__ void prep_a_kernel(const float* __restrict__ x) {
    size_t i = (size_t)blockIdx.x * blockDim.x + threadIdx.x;
    const size_t n4 = (size_t)TOKENS * DIN / 4;
    if (i >= n4) return;
    float4 v = __ldg((const float4*)x + i);
    uint32_t h0 = __half_as_ushort(__float2half_rn(v.x))
                | ((uint32_t)__half_as_ushort(__float2half_rn(v.y)) << 16);
    uint32_t h1 = __half_as_ushort(__float2half_rn(v.z))
                | ((uint32_t)__half_as_ushort(__float2half_rn(v.w)) << 16);
    uint2 p; p.x = h0; p.y = h1;
    ((uint2*)g_A)[i] = p;
}
__global__ void prep_b_kernel(const float* __restrict__ w) {
    size_t i = (size_t)blockIdx.x * blockDim.x + threadIdx.x;
    const size_t n4 = (size_t)DOUT * DIN / 4;
    if (i >= n4) return;
    float4 v = __ldg((const float4*)w + i);
    uint32_t s0 = (v.x >= 0.0f) ? 0x3C00u : 0xBC00u;
    uint32_t s1 = (v.y >= 0.0f) ? 0x3C00u : 0xBC00u;
    uint32_t s2 = (v.z >= 0.0f) ? 0x3C00u : 0xBC00u;
    uint32_t s3 = (v.w >= 0.0f) ? 0x3C00u : 0xBC00u;
    uint2 p; p.x = s0 | (s1 << 16); p.y = s2 | (s3 << 16);
    ((uint2*)g_Bs)[i] = p;
}

// ============================ GEMM kernel ===================================
__global__ void __launch_bounds__(THREADS, 2)
qat_gemm_kernel(const float* __restrict__ scale, const float* __restrict__ bias,
                float* __restrict__ out) {
    extern __shared__ char smem[];
    const uint32_t sbase = smem_u32(smem);
    const int tid  = threadIdx.x;
    const int wid  = tid >> 5;
    const int lane = tid & 31;
    const int bid  = blockIdx.x;

    // per-CTA k-phase rotation (R7 win, kept): anti-align co-resident CTAs
    const int coff = (bid & 1) ? (NCHUNK / 2) : 0;

    // tiles handled by this CTA: bid, bid+GRIDSZ, ...
    const int ntiles = (TOTAL_TILES - bid + GRIDSZ - 1) / GRIDSZ;
    const int total_slots = ntiles << 6;          // * NCHUNK

    // warp tile: 32 (m) x 64 (n); warps: 4 (m) x 2 (n)
    const int warp_m = wid & 3;
    const int warp_n = wid >> 2;
    const int wm0 = warp_m * 32;
    const int wn0 = warp_n * 64;

    // ---- per-thread invariant load geometry ----
    const int g_row = tid >> 3;               // 0..31
    const int g_chk = tid & 7;
    const size_t thr_off = (size_t)g_row * DIN + g_chk * 8;
    const uint32_t sO0 = sw_off(g_row,      g_chk);
    const uint32_t sO1 = sw_off(g_row + 32, g_chk);
    const uint32_t sO2 = sw_off(g_row + 64, g_chk);
    const uint32_t sO3 = sw_off(g_row + 96, g_chk);

    // linear tile id -> tile origin (GROUP_M = 8 swizzle; 64 m x 128 n tiles)
    auto tile_mn = [&](int lt, int& m0, int& n0) {
        const int tileid = bid + lt * GRIDSZ;
        const int group = tileid >> 10;           // / (8*128)
        const int inb   = tileid & 1023;
        m0 = ((group << 3) + (inb & 7)) * BM;
        n0 = (inb >> 3) * BN;
    };

    // flat slot -> (tile, chunk); ALWAYS commits exactly one group
    auto issue_slot = [&](int slot) {
        if (slot < total_slots) {
            const int lt = slot >> 6;
            const int cc = slot & 63;
            const int c  = (cc + coff) & (NCHUNK - 1);
            int m0, n0; tile_mn(lt, m0, n0);
            const int s = slot % STAGES;
            const uint32_t stA = sbase + s * STAGE_B;
            const uint32_t stB = stA + A_STAGE_B;
            const __half* pA = g_A  + (size_t)m0 * DIN + thr_off + (size_t)c * BK;
            const __half* pB = g_Bs + (size_t)n0 * DIN + thr_off + (size_t)c * BK;
            cp_async16(stA + sO0, pA);
            cp_async16(stA + sO1, pA + (size_t)32 * DIN);
            cp_async16(stA + sO2, pA + (size_t)64 * DIN);
            cp_async16(stA + sO3, pA + (size_t)96 * DIN);
            cp_async16(stB + sO0, pB);
            cp_async16(stB + sO1, pB + (size_t)32 * DIN);
            cp_async16(stB + sO2, pB + (size_t)64 * DIN);
            cp_async16(stB + sO3, pB + (size_t)96 * DIN);
        }
        cp_commit();
    };

    // ---- prologue: fill STAGES-1 slots ----
#pragma unroll
    for (int s = 0; s < STAGES - 1; ++s) issue_slot(s);

    // ---- accumulators: 2 m-frags x 8 n-frags x 4 ----
    float acc[2][8][4];
#pragma unroll
    for (int i = 0; i < 2; ++i)
#pragma unroll
        for (int j = 0; j < 8; ++j)
#pragma unroll
            for (int q = 0; q < 4; ++q) acc[i][j][q] = 0.0f;

    const int lquad = lane >> 3;
    const int lrow  = lane & 7;
    const int tq = lane >> 2;                 // epilogue row
    const int tr = lane & 3;                  // epilogue col pair

#pragma unroll 1
    for (int slot = 0; slot < total_slots; ++slot) {
        cp_wait<STAGES - 2>();
        __syncthreads();   // all warps done reading slot-1's stage

        issue_slot(slot + STAGES - 1);        // may belong to the NEXT tile

        const uint32_t stA = sbase + (slot % STAGES) * STAGE_B;
        const uint32_t stB = stA + A_STAGE_B;

#pragma unroll
        for (int kh = 0; kh < 4; ++kh) {      // four k16 halves of BK=64
            const int kchunk = kh * 2;

            uint32_t afr[2][4];
#pragma unroll
            for (int mi = 0; mi < 2; ++mi) {
                int row = wm0 + mi * 16 + lrow + ((lquad & 1) << 3);
                int chk = kchunk + (lquad >> 1);
                ldmatrix_x4(afr[mi][0], afr[mi][1], afr[mi][2], afr[mi][3],
                            stA + sw_off(row, chk));
            }
            uint32_t bfr[8][2];
#pragma unroll
            for (int jp = 0; jp < 4; ++jp) {
                int row = wn0 + jp * 16 + lrow + ((lquad >> 1) << 3);
                int chk = kchunk + (lquad & 1);
                uint32_t r0, r1, r2, r3;
                ldmatrix_x4(r0, r1, r2, r3, stB + sw_off(row, chk));
                bfr[jp * 2 + 0][0] = r0; bfr[jp * 2 + 0][1] = r1;
                bfr[jp * 2 + 1][0] = r2; bfr[jp * 2 + 1][1] = r3;
            }
#pragma unroll
            for (int mi = 0; mi < 2; ++mi)
#pragma unroll
                for (int j = 0; j < 8; ++j)
                    mma_16816(acc[mi][j], afr[mi], bfr[j]);
        }

        // ---- tile boundary: epilogue overlaps next tile's in-flight loads --
        if ((slot & 63) == 63) {
            int m0, n0; tile_mn(slot >> 6, m0, n0);
#pragma unroll
            for (int j = 0; j < 8; ++j) {
                const int n = n0 + wn0 + j * 8 + 2 * tr;
                const float2 sc = *(const float2*)(scale + n);
                const float2 bb = *(const float2*)(bias + n);
#pragma unroll
                for (int mi = 0; mi < 2; ++mi) {
                    const int mrow = m0 + wm0 + mi * 16 + tq;
                    float2 v0, v1;
                    v0.x = fmaf(sc.x, acc[mi][j][0], bb.x);
                    v0.y = fmaf(sc.y, acc[mi][j][1], bb.y);
                    v1.x = fmaf(sc.x, acc[mi][j][2], bb.x);
                    v1.y = fmaf(sc.y, acc[mi][j][3], bb.y);
                    *(float2*)(out + (size_t)mrow * DOUT + n) = v0;
                    *(float2*)(out + (size_t)(mrow + 8) * DOUT + n) = v1;
                    acc[mi][j][0] = 0.0f; acc[mi][j][1] = 0.0f;
                    acc[mi][j][2] = 0.0f; acc[mi][j][3] = 0.0f;
                }
            }
        }
    }
}

// ============================ launch ========================================
extern "C" void kernel_launch(void* const* d_in, const int* in_sizes, int n_in,
                              void* d_out, int out_size) {
    (void)in_sizes; (void)n_in; (void)out_size;
    const float* x     = (const float*)d_in[0];
    const float* w     = (const float*)d_in[1];
    const float* scale = (const float*)d_in[2];
    const float* b     = (const float*)d_in[3];
    float* out = (float*)d_out;

    {
        size_t n4 = (size_t)TOKENS * DIN / 4;
        prep_a_kernel<<<(unsigned)((n4 + 255) / 256), 256>>>(x);
    }
    {
        size_t n4 = (size_t)DOUT * DIN / 4;
        prep_b_kernel<<<(unsigned)((n4 + 255) / 256), 256>>>(w);
    }

    cudaFuncSetAttribute(qat_gemm_kernel,
                         cudaFuncAttributeMaxDynamicSharedMemorySize,
                         SMEM_TOTAL);
    qat_gemm_kernel<<<GRIDSZ, THREADS, SMEM_TOTAL>>>(scale, b, out);
}

// round 11
// speedup vs baseline: 1.3391x; 1.0784x over previous
#include <cuda_runtime.h>
#include <cuda_fp16.h>
#include <cstdint>

// ============================================================================
// QATLinear: y[t,o] = scale[o] * sum_i x[t,i]*sign(w[o,i]) + b[o]
//
// sign(W)=+-1 exact in fp16; x as fp16, fp32 mma.sync accumulation.
// R11 = R7 skeleton (best: 2368us, 89% of HMMA issue floor) + micro:
//  (1) all A-fragments for the chunk hoisted before the kh loop (higher LDSM
//      MLP in the post-barrier window), regs ~124 < 128 cap;
//  (2) prep_a/prep_b fused into one launch.
// Config: BM=BN=128, BK=64, 8 warps (32x64 tile), STAGES=3 (96KB/CTA),
// 2 CTAs/SM, one barrier per chunk, wave-parity k-phase stagger.
// ============================================================================

#define TOKENS 8192
#define DIN    4096
#define DOUT   16384

static constexpr int BM = 128;
static constexpr int BN = 128;
static constexpr int BK = 64;
static constexpr int STAGES = 3;
static constexpr int THREADS = 256;              // 8 warps: 4 (m) x 2 (n)
static constexpr int NCHUNK = DIN / BK;          // 64

static constexpr int A_STAGE_B = BM * BK * 2;    // 16384 B
static constexpr int B_STAGE_B = BN * BK * 2;    // 16384 B
static constexpr int STAGE_B   = A_STAGE_B + B_STAGE_B;   // 32768
static constexpr int SMEM_TOTAL = STAGES * STAGE_B;       // 98304 per CTA

// ---- scratch (device globals: allocation-free rule) ----
__device__ __half g_A [(size_t)TOKENS * DIN];    // 64 MB  (x as fp16)
__device__ __half g_Bs[(size_t)DOUT  * DIN];     // 128 MB (sign(w) as fp16)

// ============================ PTX helpers ===================================
__device__ __forceinline__ uint32_t smem_u32(const void* p) {
    uint32_t a;
    asm("{ .reg .u64 t; cvta.to.shared.u64 t, %1; cvt.u32.u64 %0, t; }"
        : "=r"(a) : "l"(p));
    return a;
}
__device__ __forceinline__ void cp_async16(uint32_t saddr, const void* gptr) {
    asm volatile("cp.async.cg.shared.global [%0], [%1], 16;"
                 :: "r"(saddr), "l"(gptr) : "memory");
}
__device__ __forceinline__ void cp_commit() {
    asm volatile("cp.async.commit_group;" ::: "memory");
}
template <int N>
__device__ __forceinline__ void cp_wait() {
    asm volatile("cp.async.wait_group %0;" :: "n"(N) : "memory");
}
__device__ __forceinline__ void ldmatrix_x4(uint32_t& r0, uint32_t& r1,
                                            uint32_t& r2, uint32_t& r3,
                                            uint32_t addr) {
    asm volatile("ldmatrix.sync.aligned.m8n8.x4.shared.b16 {%0,%1,%2,%3}, [%4];"
                 : "=r"(r0), "=r"(r1), "=r"(r2), "=r"(r3) : "r"(addr));
}
__device__ __forceinline__ void mma_16816(float* c, const uint32_t* a,
                                          const uint32_t* b) {
    asm volatile(
        "mma.sync.aligned.m16n8k16.row.col.f32.f16.f16.f32 "
        "{%0,%1,%2,%3}, {%4,%5,%6,%7}, {%8,%9}, {%0,%1,%2,%3};"
        : "+f"(c[0]), "+f"(c[1]), "+f"(c[2]), "+f"(c[3])
        : "r"(a[0]), "r"(a[1]), "r"(a[2]), "r"(a[3]), "r"(b[0]), "r"(b[1]));
}
// tile rows: 64 fp16 = 128 B = 8 x 16B chunks; chunk' = chunk ^ (row&7)
__device__ __forceinline__ uint32_t sw_off(int row, int chunk) {
    return (uint32_t)((row << 7) + ((chunk ^ (row & 7)) << 4));
}

// ===================== fused prep kernel (one launch) =======================
// blocks [0, NA) convert x -> fp16; blocks [NA, NA+NB) convert w -> sign fp16
static constexpr unsigned PREP_NA = (unsigned)(((size_t)TOKENS * DIN / 4 + 255) / 256);
static constexpr unsigned PREP_NB = (unsigned)(((size_t)DOUT  * DIN / 4 + 255) / 256);

__global__ void prep_fused_kernel(const float* __restrict__ x,
                                  const float* __restrict__ w) {
    const unsigned b = blockIdx.x;
    if (b < PREP_NA) {
        size_t i = (size_t)b * blockDim.x + threadIdx.x;
        if (i >= (size_t)TOKENS * DIN / 4) return;
        float4 v = __ldg((const float4*)x + i);
        uint32_t h0 = __half_as_ushort(__float2half_rn(v.x))
                    | ((uint32_t)__half_as_ushort(__float2half_rn(v.y)) << 16);
        uint32_t h1 = __half_as_ushort(__float2half_rn(v.z))
                    | ((uint32_t)__half_as_ushort(__float2half_rn(v.w)) << 16);
        uint2 p; p.x = h0; p.y = h1;
        ((uint2*)g_A)[i] = p;
    } else {
        size_t i = (size_t)(b - PREP_NA) * blockDim.x + threadIdx.x;
        if (i >= (size_t)DOUT * DIN / 4) return;
        float4 v = __ldg((const float4*)w + i);
        // sign with 0 -> +1 ; fp16 +1.0 = 0x3C00, -1.0 = 0xBC00
        uint32_t s0 = (v.x >= 0.0f) ? 0x3C00u : 0xBC00u;
        uint32_t s1 = (v.y >= 0.0f) ? 0x3C00u : 0xBC00u;
        uint32_t s2 = (v.z >= 0.0f) ? 0x3C00u : 0xBC00u;
        uint32_t s3 = (v.w >= 0.0f) ? 0x3C00u : 0xBC00u;
        uint2 p; p.x = s0 | (s1 << 16); p.y = s2 | (s3 << 16);
        ((uint2*)g_Bs)[i] = p;
    }
}

// ============================ GEMM kernel ===================================
__global__ void __launch_bounds__(THREADS, 2)
qat_gemm_kernel(const float* __restrict__ scale, const float* __restrict__ bias,
                float* __restrict__ out) {
    extern __shared__ char smem[];
    const uint32_t sbase = smem_u32(smem);
    const int tid  = threadIdx.x;
    const int wid  = tid >> 5;
    const int lane = tid & 31;

    // grouped tile swizzle (GROUP_M = 8): 64 m-tiles x 128 n-tiles
    const int pid   = blockIdx.x;                 // 0 .. 8191
    const int group = pid >> 10;
    const int inb   = pid & 1023;
    const int pid_m = (group << 3) + (inb & 7);
    const int pid_n = inb >> 3;
    const int m0 = pid_m * BM;
    const int n0 = pid_n * BN;

    // phase stagger: wave partners anti-align k-loops
    const int coff = ((pid / 148) & 1) ? (NCHUNK / 2) : 0;

    // warp tile: 32 (m) x 64 (n); warps: 4 (m) x 2 (n)
    const int warp_m = wid & 3;
    const int warp_n = wid >> 2;
    const int wm0 = warp_m * 32;
    const int wn0 = warp_n * 64;

    // ---- global load indices (16B per cp.async; rows are 8x16B chunks) ----
    const int g_row = tid >> 3;               // 0..31
    const int g_chk = tid & 7;

    const __half* gA0 = g_A  + (size_t)(m0 + g_row) * DIN + g_chk * 8;
    const __half* gA1 = gA0 + (size_t)32 * DIN;
    const __half* gA2 = gA0 + (size_t)64 * DIN;
    const __half* gA3 = gA0 + (size_t)96 * DIN;
    const __half* gB0 = g_Bs + (size_t)(n0 + g_row) * DIN + g_chk * 8;
    const __half* gB1 = gB0 + (size_t)32 * DIN;
    const __half* gB2 = gB0 + (size_t)64 * DIN;
    const __half* gB3 = gB0 + (size_t)96 * DIN;

    const uint32_t sO0 = sw_off(g_row,      g_chk);
    const uint32_t sO1 = sw_off(g_row + 32, g_chk);
    const uint32_t sO2 = sw_off(g_row + 64, g_chk);
    const uint32_t sO3 = sw_off(g_row + 96, g_chk);

    auto issue_stage = [&](int cc) {
        const int s = cc % STAGES;
        const int c = (cc + coff) & (NCHUNK - 1);
        const uint32_t stA = sbase + s * STAGE_B;
        const uint32_t stB = stA + A_STAGE_B;
        const size_t kofs = (size_t)c * BK;
        cp_async16(stA + sO0, gA0 + kofs);
        cp_async16(stA + sO1, gA1 + kofs);
        cp_async16(stA + sO2, gA2 + kofs);
        cp_async16(stA + sO3, gA3 + kofs);
        cp_async16(stB + sO0, gB0 + kofs);
        cp_async16(stB + sO1, gB1 + kofs);
        cp_async16(stB + sO2, gB2 + kofs);
        cp_async16(stB + sO3, gB3 + kofs);
    };

    // ---- prologue: fill STAGES-1 stages ----
#pragma unroll
    for (int cc = 0; cc < STAGES - 1; ++cc) { issue_stage(cc); cp_commit(); }

    // ---- accumulators: 2 m-frags x 8 n-frags x 4 ----
    float acc[2][8][4];
#pragma unroll
    for (int i = 0; i < 2; ++i)
#pragma unroll
        for (int j = 0; j < 8; ++j)
#pragma unroll
            for (int q = 0; q < 4; ++q) acc[i][j][q] = 0.0f;

    const int lquad = lane >> 3;
    const int lrow  = lane & 7;

#pragma unroll 1
    for (int cc = 0; cc < NCHUNK; ++cc) {
        cp_wait<STAGES - 2>();
        __syncthreads();   // all warps done reading slot cc-1

        if (cc + STAGES - 1 < NCHUNK) issue_stage(cc + STAGES - 1);
        cp_commit();

        const uint32_t stA = sbase + (cc % STAGES) * STAGE_B;
        const uint32_t stB = stA + A_STAGE_B;

        // ---- hoist ALL A fragments for this chunk (4 kh x 2 m16 tiles) ----
        uint32_t afr[4][2][4];
#pragma unroll
        for (int kh = 0; kh < 4; ++kh) {
#pragma unroll
            for (int mi = 0; mi < 2; ++mi) {
                int row = wm0 + mi * 16 + lrow + ((lquad & 1) << 3);
                int chk = kh * 2 + (lquad >> 1);
                ldmatrix_x4(afr[kh][mi][0], afr[kh][mi][1],
                            afr[kh][mi][2], afr[kh][mi][3],
                            stA + sw_off(row, chk));
            }
        }

#pragma unroll
        for (int kh = 0; kh < 4; ++kh) {      // four k16 halves of BK=64
            const int kchunk = kh * 2;
            // B frags: 8 n8 tiles, 2 per ldmatrix.x4
            uint32_t bfr[8][2];
#pragma unroll
            for (int jp = 0; jp < 4; ++jp) {
                int row = wn0 + jp * 16 + lrow + ((lquad >> 1) << 3);
                int chk = kchunk + (lquad & 1);
                uint32_t r0, r1, r2, r3;
                ldmatrix_x4(r0, r1, r2, r3, stB + sw_off(row, chk));
                bfr[jp * 2 + 0][0] = r0; bfr[jp * 2 + 0][1] = r1;
                bfr[jp * 2 + 1][0] = r2; bfr[jp * 2 + 1][1] = r3;
            }
#pragma unroll
            for (int mi = 0; mi < 2; ++mi)
#pragma unroll
                for (int j = 0; j < 8; ++j)
                    mma_16816(acc[mi][j], afr[kh][mi], bfr[j]);
        }
    }

    // ---- epilogue: fused scale/bias, float2 stores ----
    const int tq = lane >> 2;
    const int tr = lane & 3;
#pragma unroll
    for (int j = 0; j < 8; ++j) {
        const int n = n0 + wn0 + j * 8 + 2 * tr;
        const float2 sc = *(const float2*)(scale + n);
        const float2 bb = *(const float2*)(bias + n);
#pragma unroll
        for (int mi = 0; mi < 2; ++mi) {
            const int mrow = m0 + wm0 + mi * 16 + tq;
            float2 v0, v1;
            v0.x = fmaf(sc.x, acc[mi][j][0], bb.x);
            v0.y = fmaf(sc.y, acc[mi][j][1], bb.y);
            v1.x = fmaf(sc.x, acc[mi][j][2], bb.x);
            v1.y = fmaf(sc.y, acc[mi][j][3], bb.y);
            *(float2*)(out + (size_t)mrow * DOUT + n) = v0;
            *(float2*)(out + (size_t)(mrow + 8) * DOUT + n) = v1;
        }
    }
}

// ============================ launch ========================================
extern "C" void kernel_launch(void* const* d_in, const int* in_sizes, int n_in,
                              void* d_out, int out_size) {
    (void)in_sizes; (void)n_in; (void)out_size;
    const float* x     = (const float*)d_in[0];
    const float* w     = (const float*)d_in[1];
    const float* scale = (const float*)d_in[2];
    const float* b     = (const float*)d_in[3];
    float* out = (float*)d_out;

    prep_fused_kernel<<<PREP_NA + PREP_NB, 256>>>(x, w);

    cudaFuncSetAttribute(qat_gemm_kernel,
                         cudaFuncAttributeMaxDynamicSharedMemorySize,
                         SMEM_TOTAL);
    const int grid = (TOKENS / BM) * (DOUT / BN);   // 8192
    qat_gemm_kernel<<<grid, THREADS, SMEM_TOTAL>>>(scale, b, out);
}

// round 12
// speedup vs baseline: 1.4222x; 1.0620x over previous
#include <cuda_runtime.h>
#include <cuda_fp16.h>
#include <cstdint>

// ============================================================================
// QATLinear: y[t,o] = scale[o] * sum_i x[t,i]*sign(w[o,i]) + b[o]
//
// sign(W)=+-1 exact in fp16; x as fp16, fp32 mma.sync accumulation.
// R12 = R7 inner loop (validated best schedule; R11's A-hoist hit the 128-reg
// cap and regressed -> reverted) + fused single prep launch (kept from R11)
// + micro-reorder: kh=0 fragment loads issue BEFORE the next-stage cp.asyncs,
// so the tensor stream refills immediately after the barrier instead of
// waiting behind 8 LSU issue slots.
// Config: BM=BN=128, BK=64, 8 warps (32x64 tile), STAGES=3 (96KB/CTA),
// 2 CTAs/SM (ncu-confirmed occ=24.7%), one barrier/chunk, k-phase stagger.
// ============================================================================

#define TOKENS 8192
#define DIN    4096
#define DOUT   16384

static constexpr int BM = 128;
static constexpr int BN = 128;
static constexpr int BK = 64;
static constexpr int STAGES = 3;
static constexpr int THREADS = 256;              // 8 warps: 4 (m) x 2 (n)
static constexpr int NCHUNK = DIN / BK;          // 64

static constexpr int A_STAGE_B = BM * BK * 2;    // 16384 B
static constexpr int B_STAGE_B = BN * BK * 2;    // 16384 B
static constexpr int STAGE_B   = A_STAGE_B + B_STAGE_B;   // 32768
static constexpr int SMEM_TOTAL = STAGES * STAGE_B;       // 98304 per CTA

// ---- scratch (device globals: allocation-free rule) ----
__device__ __half g_A [(size_t)TOKENS * DIN];    // 64 MB  (x as fp16)
__device__ __half g_Bs[(size_t)DOUT  * DIN];     // 128 MB (sign(w) as fp16)

// ============================ PTX helpers ===================================
__device__ __forceinline__ uint32_t smem_u32(const void* p) {
    uint32_t a;
    asm("{ .reg .u64 t; cvta.to.shared.u64 t, %1; cvt.u32.u64 %0, t; }"
        : "=r"(a) : "l"(p));
    return a;
}
__device__ __forceinline__ void cp_async16(uint32_t saddr, const void* gptr) {
    asm volatile("cp.async.cg.shared.global [%0], [%1], 16;"
                 :: "r"(saddr), "l"(gptr) : "memory");
}
__device__ __forceinline__ void cp_commit() {
    asm volatile("cp.async.commit_group;" ::: "memory");
}
template <int N>
__device__ __forceinline__ void cp_wait() {
    asm volatile("cp.async.wait_group %0;" :: "n"(N) : "memory");
}
__device__ __forceinline__ void ldmatrix_x4(uint32_t& r0, uint32_t& r1,
                                            uint32_t& r2, uint32_t& r3,
                                            uint32_t addr) {
    asm volatile("ldmatrix.sync.aligned.m8n8.x4.shared.b16 {%0,%1,%2,%3}, [%4];"
                 : "=r"(r0), "=r"(r1), "=r"(r2), "=r"(r3) : "r"(addr));
}
__device__ __forceinline__ void mma_16816(float* c, const uint32_t* a,
                                          const uint32_t* b) {
    asm volatile(
        "mma.sync.aligned.m16n8k16.row.col.f32.f16.f16.f32 "
        "{%0,%1,%2,%3}, {%4,%5,%6,%7}, {%8,%9}, {%0,%1,%2,%3};"
        : "+f"(c[0]), "+f"(c[1]), "+f"(c[2]), "+f"(c[3])
        : "r"(a[0]), "r"(a[1]), "r"(a[2]), "r"(a[3]), "r"(b[0]), "r"(b[1]));
}
// tile rows: 64 fp16 = 128 B = 8 x 16B chunks; chunk' = chunk ^ (row&7)
__device__ __forceinline__ uint32_t sw_off(int row, int chunk) {
    return (uint32_t)((row << 7) + ((chunk ^ (row & 7)) << 4));
}

// ===================== fused prep kernel (one launch) =======================
static constexpr unsigned PREP_NA = (unsigned)(((size_t)TOKENS * DIN / 4 + 255) / 256);
static constexpr unsigned PREP_NB = (unsigned)(((size_t)DOUT  * DIN / 4 + 255) / 256);

__global__ void prep_fused_kernel(const float* __restrict__ x,
                                  const float* __restrict__ w) {
    const unsigned b = blockIdx.x;
    if (b < PREP_NA) {
        size_t i = (size_t)b * blockDim.x + threadIdx.x;
        if (i >= (size_t)TOKENS * DIN / 4) return;
        float4 v = __ldg((const float4*)x + i);
        uint32_t h0 = __half_as_ushort(__float2half_rn(v.x))
                    | ((uint32_t)__half_as_ushort(__float2half_rn(v.y)) << 16);
        uint32_t h1 = __half_as_ushort(__float2half_rn(v.z))
                    | ((uint32_t)__half_as_ushort(__float2half_rn(v.w)) << 16);
        uint2 p; p.x = h0; p.y = h1;
        ((uint2*)g_A)[i] = p;
    } else {
        size_t i = (size_t)(b - PREP_NA) * blockDim.x + threadIdx.x;
        if (i >= (size_t)DOUT * DIN / 4) return;
        float4 v = __ldg((const float4*)w + i);
        // sign with 0 -> +1 ; fp16 +1.0 = 0x3C00, -1.0 = 0xBC00
        uint32_t s0 = (v.x >= 0.0f) ? 0x3C00u : 0xBC00u;
        uint32_t s1 = (v.y >= 0.0f) ? 0x3C00u : 0xBC00u;
        uint32_t s2 = (v.z >= 0.0f) ? 0x3C00u : 0xBC00u;
        uint32_t s3 = (v.w >= 0.0f) ? 0x3C00u : 0xBC00u;
        uint2 p; p.x = s0 | (s1 << 16); p.y = s2 | (s3 << 16);
        ((uint2*)g_Bs)[i] = p;
    }
}

// ============================ GEMM kernel ===================================
__global__ void __launch_bounds__(THREADS, 2)
qat_gemm_kernel(const float* __restrict__ scale, const float* __restrict__ bias,
                float* __restrict__ out) {
    extern __shared__ char smem[];
    const uint32_t sbase = smem_u32(smem);
    const int tid  = threadIdx.x;
    const int wid  = tid >> 5;
    const int lane = tid & 31;

    // grouped tile swizzle (GROUP_M = 8): 64 m-tiles x 128 n-tiles
    const int pid   = blockIdx.x;                 // 0 .. 8191
    const int group = pid >> 10;
    const int inb   = pid & 1023;
    const int pid_m = (group << 3) + (inb & 7);
    const int pid_n = inb >> 3;
    const int m0 = pid_m * BM;
    const int n0 = pid_n * BN;

    // phase stagger: wave partners anti-align k-loops
    const int coff = ((pid / 148) & 1) ? (NCHUNK / 2) : 0;

    // warp tile: 32 (m) x 64 (n); warps: 4 (m) x 2 (n)
    const int warp_m = wid & 3;
    const int warp_n = wid >> 2;
    const int wm0 = warp_m * 32;
    const int wn0 = warp_n * 64;

    // ---- global load indices (16B per cp.async; rows are 8x16B chunks) ----
    const int g_row = tid >> 3;               // 0..31
    const int g_chk = tid & 7;

    const __half* gA0 = g_A  + (size_t)(m0 + g_row) * DIN + g_chk * 8;
    const __half* gA1 = gA0 + (size_t)32 * DIN;
    const __half* gA2 = gA0 + (size_t)64 * DIN;
    const __half* gA3 = gA0 + (size_t)96 * DIN;
    const __half* gB0 = g_Bs + (size_t)(n0 + g_row) * DIN + g_chk * 8;
    const __half* gB1 = gB0 + (size_t)32 * DIN;
    const __half* gB2 = gB0 + (size_t)64 * DIN;
    const __half* gB3 = gB0 + (size_t)96 * DIN;

    const uint32_t sO0 = sw_off(g_row,      g_chk);
    const uint32_t sO1 = sw_off(g_row + 32, g_chk);
    const uint32_t sO2 = sw_off(g_row + 64, g_chk);
    const uint32_t sO3 = sw_off(g_row + 96, g_chk);

    auto issue_stage = [&](int cc) {
        const int s = cc % STAGES;
        const int c = (cc + coff) & (NCHUNK - 1);
        const uint32_t stA = sbase + s * STAGE_B;
        const uint32_t stB = stA + A_STAGE_B;
        const size_t kofs = (size_t)c * BK;
        cp_async16(stA + sO0, gA0 + kofs);
        cp_async16(stA + sO1, gA1 + kofs);
        cp_async16(stA + sO2, gA2 + kofs);
        cp_async16(stA + sO3, gA3 + kofs);
        cp_async16(stB + sO0, gB0 + kofs);
        cp_async16(stB + sO1, gB1 + kofs);
        cp_async16(stB + sO2, gB2 + kofs);
        cp_async16(stB + sO3, gB3 + kofs);
    };

    // ---- prologue: fill STAGES-1 stages ----
#pragma unroll
    for (int cc = 0; cc < STAGES - 1; ++cc) { issue_stage(cc); cp_commit(); }

    // ---- accumulators: 2 m-frags x 8 n-frags x 4 ----
    float acc[2][8][4];
#pragma unroll
    for (int i = 0; i < 2; ++i)
#pragma unroll
        for (int j = 0; j < 8; ++j)
#pragma unroll
            for (int q = 0; q < 4; ++q) acc[i][j][q] = 0.0f;

    const int lquad = lane >> 3;
    const int lrow  = lane & 7;

#pragma unroll 1
    for (int cc = 0; cc < NCHUNK; ++cc) {
        cp_wait<STAGES - 2>();
        __syncthreads();   // all warps done reading slot cc-1

        const uint32_t stA = sbase + (cc % STAGES) * STAGE_B;
        const uint32_t stB = stA + A_STAGE_B;

        // ---- kh=0 fragment loads FIRST (refill tensor stream immediately) --
        uint32_t afr[2][4];
        uint32_t bfr[8][2];
#pragma unroll
        for (int mi = 0; mi < 2; ++mi) {
            int row = wm0 + mi * 16 + lrow + ((lquad & 1) << 3);
            int chk = (lquad >> 1);
            ldmatrix_x4(afr[mi][0], afr[mi][1], afr[mi][2], afr[mi][3],
                        stA + sw_off(row, chk));
        }
#pragma unroll
        for (int jp = 0; jp < 4; ++jp) {
            int row = wn0 + jp * 16 + lrow + ((lquad >> 1) << 3);
            int chk = (lquad & 1);
            uint32_t r0, r1, r2, r3;
            ldmatrix_x4(r0, r1, r2, r3, stB + sw_off(row, chk));
            bfr[jp * 2 + 0][0] = r0; bfr[jp * 2 + 0][1] = r1;
            bfr[jp * 2 + 1][0] = r2; bfr[jp * 2 + 1][1] = r3;
        }

        // next-stage cp.asyncs AFTER the first fragment batch
        if (cc + STAGES - 1 < NCHUNK) issue_stage(cc + STAGES - 1);
        cp_commit();

#pragma unroll
        for (int kh = 0; kh < 4; ++kh) {      // four k16 halves of BK=64
            // MMAs on current fragments
#pragma unroll
            for (int mi = 0; mi < 2; ++mi)
#pragma unroll
                for (int j = 0; j < 8; ++j)
                    mma_16816(acc[mi][j], afr[mi], bfr[j]);

            // load kh+1 fragments (skipped on last kh)
            if (kh < 3) {
                const int kchunk = (kh + 1) * 2;
#pragma unroll
                for (int mi = 0; mi < 2; ++mi) {
                    int row = wm0 + mi * 16 + lrow + ((lquad & 1) << 3);
                    int chk = kchunk + (lquad >> 1);
                    ldmatrix_x4(afr[mi][0], afr[mi][1], afr[mi][2], afr[mi][3],
                                stA + sw_off(row, chk));
                }
#pragma unroll
                for (int jp = 0; jp < 4; ++jp) {
                    int row = wn0 + jp * 16 + lrow + ((lquad >> 1) << 3);
                    int chk = kchunk + (lquad & 1);
                    uint32_t r0, r1, r2, r3;
                    ldmatrix_x4(r0, r1, r2, r3, stB + sw_off(row, chk));
                    bfr[jp * 2 + 0][0] = r0; bfr[jp * 2 + 0][1] = r1;
                    bfr[jp * 2 + 1][0] = r2; bfr[jp * 2 + 1][1] = r3;
                }
            }
        }
    }

    // ---- epilogue: fused scale/bias, float2 stores ----
    const int tq = lane >> 2;
    const int tr = lane & 3;
#pragma unroll
    for (int j = 0; j < 8; ++j) {
        const int n = n0 + wn0 + j * 8 + 2 * tr;
        const float2 sc = *(const float2*)(scale + n);
        const float2 bb = *(const float2*)(bias + n);
#pragma unroll
        for (int mi = 0; mi < 2; ++mi) {
            const int mrow = m0 + wm0 + mi * 16 + tq;
            float2 v0, v1;
            v0.x = fmaf(sc.x, acc[mi][j][0], bb.x);
            v0.y = fmaf(sc.y, acc[mi][j][1], bb.y);
            v1.x = fmaf(sc.x, acc[mi][j][2], bb.x);
            v1.y = fmaf(sc.y, acc[mi][j][3], bb.y);
            *(float2*)(out + (size_t)mrow * DOUT + n) = v0;
            *(float2*)(out + (size_t)(mrow + 8) * DOUT + n) = v1;
        }
    }
}

// ============================ launch ========================================
extern "C" void kernel_launch(void* const* d_in, const int* in_sizes, int n_in,
                              void* d_out, int out_size) {
    (void)in_sizes; (void)n_in; (void)out_size;
    const float* x     = (const float*)d_in[0];
    const float* w     = (const float*)d_in[1];
    const float* scale = (const float*)d_in[2];
    const float* b     = (const float*)d_in[3];
    float* out = (float*)d_out;

    prep_fused_kernel<<<PREP_NA + PREP_NB, 256>>>(x, w);

    cudaFuncSetAttribute(qat_gemm_kernel,
                         cudaFuncAttributeMaxDynamicSharedMemorySize,
                         SMEM_TOTAL);
    const int grid = (TOKENS / BM) * (DOUT / BN);   // 8192
    qat_gemm_kernel<<<grid, THREADS, SMEM_TOTAL>>>(scale, b, out);
}

// round 13
// speedup vs baseline: 1.4261x; 1.0028x over previous
#include <cuda_runtime.h>
#include <cuda_fp16.h>
#include <cstdint>

// ============================================================================
// QATLinear: y[t,o] = scale[o] * sum_i x[t,i]*sign(w[o,i]) + b[o]
//
// sign(W)=+-1 exact in fp16; x as fp16, fp32 mma.sync accumulation.
// R13 = R12 (best, 2349us, ncu: tensor=80.2%) + ONE surgical change:
// scale/bias for this tile prefetched to smem via cp.async in the prologue
// (bundled with stage-0's commit group, zero added latency) and read via LDS
// in the epilogue -- removes ~600cyc of exposed LDG latency at each tile end.
// Inner loop byte-identical to R12 (ptxas schedule at 128-reg cap is fragile).
// Config: BM=BN=128, BK=64, 8 warps (32x64 tile), STAGES=3, 2 CTAs/SM,
// one barrier/chunk, k-phase stagger, kh-level fragment double buffering.
// ============================================================================

#define TOKENS 8192
#define DIN    4096
#define DOUT   16384

static constexpr int BM = 128;
static constexpr int BN = 128;
static constexpr int BK = 64;
static constexpr int STAGES = 3;
static constexpr int THREADS = 256;              // 8 warps: 4 (m) x 2 (n)
static constexpr int NCHUNK = DIN / BK;          // 64

static constexpr int A_STAGE_B = BM * BK * 2;    // 16384 B
static constexpr int B_STAGE_B = BN * BK * 2;    // 16384 B
static constexpr int STAGE_B   = A_STAGE_B + B_STAGE_B;   // 32768
static constexpr int SCB_OFF   = STAGES * STAGE_B;        // 98304
static constexpr int SMEM_TOTAL = SCB_OFF + 1024;         // 99328 per CTA

// ---- scratch (device globals: allocation-free rule) ----
__device__ __half g_A [(size_t)TOKENS * DIN];    // 64 MB  (x as fp16)
__device__ __half g_Bs[(size_t)DOUT  * DIN];     // 128 MB (sign(w) as fp16)

// ============================ PTX helpers ===================================
__device__ __forceinline__ uint32_t smem_u32(const void* p) {
    uint32_t a;
    asm("{ .reg .u64 t; cvta.to.shared.u64 t, %1; cvt.u32.u64 %0, t; }"
        : "=r"(a) : "l"(p));
    return a;
}
__device__ __forceinline__ void cp_async16(uint32_t saddr, const void* gptr) {
    asm volatile("cp.async.cg.shared.global [%0], [%1], 16;"
                 :: "r"(saddr), "l"(gptr) : "memory");
}
__device__ __forceinline__ void cp_commit() {
    asm volatile("cp.async.commit_group;" ::: "memory");
}
template <int N>
__device__ __forceinline__ void cp_wait() {
    asm volatile("cp.async.wait_group %0;" :: "n"(N) : "memory");
}
__device__ __forceinline__ void ldmatrix_x4(uint32_t& r0, uint32_t& r1,
                                            uint32_t& r2, uint32_t& r3,
                                            uint32_t addr) {
    asm volatile("ldmatrix.sync.aligned.m8n8.x4.shared.b16 {%0,%1,%2,%3}, [%4];"
                 : "=r"(r0), "=r"(r1), "=r"(r2), "=r"(r3) : "r"(addr));
}
__device__ __forceinline__ void mma_16816(float* c, const uint32_t* a,
                                          const uint32_t* b) {
    asm volatile(
        "mma.sync.aligned.m16n8k16.row.col.f32.f16.f16.f32 "
        "{%0,%1,%2,%3}, {%4,%5,%6,%7}, {%8,%9}, {%0,%1,%2,%3};"
        : "+f"(c[0]), "+f"(c[1]), "+f"(c[2]), "+f"(c[3])
        : "r"(a[0]), "r"(a[1]), "r"(a[2]), "r"(a[3]), "r"(b[0]), "r"(b[1]));
}
// tile rows: 64 fp16 = 128 B = 8 x 16B chunks; chunk' = chunk ^ (row&7)
__device__ __forceinline__ uint32_t sw_off(int row, int chunk) {
    return (uint32_t)((row << 7) + ((chunk ^ (row & 7)) << 4));
}

// ===================== fused prep kernel (one launch) =======================
static constexpr unsigned PREP_NA = (unsigned)(((size_t)TOKENS * DIN / 4 + 255) / 256);
static constexpr unsigned PREP_NB = (unsigned)(((size_t)DOUT  * DIN / 4 + 255) / 256);

__global__ void prep_fused_kernel(const float* __restrict__ x,
                                  const float* __restrict__ w) {
    const unsigned b = blockIdx.x;
    if (b < PREP_NA) {
        size_t i = (size_t)b * blockDim.x + threadIdx.x;
        if (i >= (size_t)TOKENS * DIN / 4) return;
        float4 v = __ldg((const float4*)x + i);
        uint32_t h0 = __half_as_ushort(__float2half_rn(v.x))
                    | ((uint32_t)__half_as_ushort(__float2half_rn(v.y)) << 16);
        uint32_t h1 = __half_as_ushort(__float2half_rn(v.z))
                    | ((uint32_t)__half_as_ushort(__float2half_rn(v.w)) << 16);
        uint2 p; p.x = h0; p.y = h1;
        ((uint2*)g_A)[i] = p;
    } else {
        size_t i = (size_t)(b - PREP_NA) * blockDim.x + threadIdx.x;
        if (i >= (size_t)DOUT * DIN / 4) return;
        float4 v = __ldg((const float4*)w + i);
        // sign with 0 -> +1 ; fp16 +1.0 = 0x3C00, -1.0 = 0xBC00
        uint32_t s0 = (v.x >= 0.0f) ? 0x3C00u : 0xBC00u;
        uint32_t s1 = (v.y >= 0.0f) ? 0x3C00u : 0xBC00u;
        uint32_t s2 = (v.z >= 0.0f) ? 0x3C00u : 0xBC00u;
        uint32_t s3 = (v.w >= 0.0f) ? 0x3C00u : 0xBC00u;
        uint2 p; p.x = s0 | (s1 << 16); p.y = s2 | (s3 << 16);
        ((uint2*)g_Bs)[i] = p;
    }
}

// ============================ GEMM kernel ===================================
__global__ void __launch_bounds__(THREADS, 2)
qat_gemm_kernel(const float* __restrict__ scale, const float* __restrict__ bias,
                float* __restrict__ out) {
    extern __shared__ char smem[];
    const uint32_t sbase = smem_u32(smem);
    const int tid  = threadIdx.x;
    const int wid  = tid >> 5;
    const int lane = tid & 31;

    // grouped tile swizzle (GROUP_M = 8): 64 m-tiles x 128 n-tiles
    const int pid   = blockIdx.x;                 // 0 .. 8191
    const int group = pid >> 10;
    const int inb   = pid & 1023;
    const int pid_m = (group << 3) + (inb & 7);
    const int pid_n = inb >> 3;
    const int m0 = pid_m * BM;
    const int n0 = pid_n * BN;

    // phase stagger: wave partners anti-align k-loops
    const int coff = ((pid / 148) & 1) ? (NCHUNK / 2) : 0;

    // warp tile: 32 (m) x 64 (n); warps: 4 (m) x 2 (n)
    const int warp_m = wid & 3;
    const int warp_n = wid >> 2;
    const int wm0 = warp_m * 32;
    const int wn0 = warp_n * 64;

    // ---- global load indices (16B per cp.async; rows are 8x16B chunks) ----
    const int g_row = tid >> 3;               // 0..31
    const int g_chk = tid & 7;

    const __half* gA0 = g_A  + (size_t)(m0 + g_row) * DIN + g_chk * 8;
    const __half* gA1 = gA0 + (size_t)32 * DIN;
    const __half* gA2 = gA0 + (size_t)64 * DIN;
    const __half* gA3 = gA0 + (size_t)96 * DIN;
    const __half* gB0 = g_Bs + (size_t)(n0 + g_row) * DIN + g_chk * 8;
    const __half* gB1 = gB0 + (size_t)32 * DIN;
    const __half* gB2 = gB0 + (size_t)64 * DIN;
    const __half* gB3 = gB0 + (size_t)96 * DIN;

    const uint32_t sO0 = sw_off(g_row,      g_chk);
    const uint32_t sO1 = sw_off(g_row + 32, g_chk);
    const uint32_t sO2 = sw_off(g_row + 64, g_chk);
    const uint32_t sO3 = sw_off(g_row + 96, g_chk);

    auto issue_stage = [&](int cc) {
        const int s = cc % STAGES;
        const int c = (cc + coff) & (NCHUNK - 1);
        const uint32_t stA = sbase + s * STAGE_B;
        const uint32_t stB = stA + A_STAGE_B;
        const size_t kofs = (size_t)c * BK;
        cp_async16(stA + sO0, gA0 + kofs);
        cp_async16(stA + sO1, gA1 + kofs);
        cp_async16(stA + sO2, gA2 + kofs);
        cp_async16(stA + sO3, gA3 + kofs);
        cp_async16(stB + sO0, gB0 + kofs);
        cp_async16(stB + sO1, gB1 + kofs);
        cp_async16(stB + sO2, gB2 + kofs);
        cp_async16(stB + sO3, gB3 + kofs);
    };

    // ---- prologue: scale/bias prefetch bundled with stage 0's group ----
    if (tid < 32)       cp_async16(sbase + SCB_OFF + tid * 16,
                                   scale + n0 + tid * 4);
    else if (tid < 64)  cp_async16(sbase + SCB_OFF + 512 + (tid - 32) * 16,
                                   bias + n0 + (tid - 32) * 4);
    issue_stage(0); cp_commit();
#pragma unroll
    for (int cc = 1; cc < STAGES - 1; ++cc) { issue_stage(cc); cp_commit(); }

    // ---- accumulators: 2 m-frags x 8 n-frags x 4 ----
    float acc[2][8][4];
#pragma unroll
    for (int i = 0; i < 2; ++i)
#pragma unroll
        for (int j = 0; j < 8; ++j)
#pragma unroll
            for (int q = 0; q < 4; ++q) acc[i][j][q] = 0.0f;

    const int lquad = lane >> 3;
    const int lrow  = lane & 7;

#pragma unroll 1
    for (int cc = 0; cc < NCHUNK; ++cc) {
        cp_wait<STAGES - 2>();
        __syncthreads();   // all warps done reading slot cc-1

        const uint32_t stA = sbase + (cc % STAGES) * STAGE_B;
        const uint32_t stB = stA + A_STAGE_B;

        // ---- kh=0 fragment loads FIRST (refill tensor stream immediately) --
        uint32_t afr[2][4];
        uint32_t bfr[8][2];
#pragma unroll
        for (int mi = 0; mi < 2; ++mi) {
            int row = wm0 + mi * 16 + lrow + ((lquad & 1) << 3);
            int chk = (lquad >> 1);
            ldmatrix_x4(afr[mi][0], afr[mi][1], afr[mi][2], afr[mi][3],
                        stA + sw_off(row, chk));
        }
#pragma unroll
        for (int jp = 0; jp < 4; ++jp) {
            int row = wn0 + jp * 16 + lrow + ((lquad >> 1) << 3);
            int chk = (lquad & 1);
            uint32_t r0, r1, r2, r3;
            ldmatrix_x4(r0, r1, r2, r3, stB + sw_off(row, chk));
            bfr[jp * 2 + 0][0] = r0; bfr[jp * 2 + 0][1] = r1;
            bfr[jp * 2 + 1][0] = r2; bfr[jp * 2 + 1][1] = r3;
        }

        // next-stage cp.asyncs AFTER the first fragment batch
        if (cc + STAGES - 1 < NCHUNK) issue_stage(cc + STAGES - 1);
        cp_commit();

#pragma unroll
        for (int kh = 0; kh < 4; ++kh) {      // four k16 halves of BK=64
            // MMAs on current fragments
#pragma unroll
            for (int mi = 0; mi < 2; ++mi)
#pragma unroll
                for (int j = 0; j < 8; ++j)
                    mma_16816(acc[mi][j], afr[mi], bfr[j]);

            // load kh+1 fragments (skipped on last kh)
            if (kh < 3) {
                const int kchunk = (kh + 1) * 2;
#pragma unroll
                for (int mi = 0; mi < 2; ++mi) {
                    int row = wm0 + mi * 16 + lrow + ((lquad & 1) << 3);
                    int chk = kchunk + (lquad >> 1);
                    ldmatrix_x4(afr[mi][0], afr[mi][1], afr[mi][2], afr[mi][3],
                                stA + sw_off(row, chk));
                }
#pragma unroll
                for (int jp = 0; jp < 4; ++jp) {
                    int row = wn0 + jp * 16 + lrow + ((lquad >> 1) << 3);
                    int chk = kchunk + (lquad & 1);
                    uint32_t r0, r1, r2, r3;
                    ldmatrix_x4(r0, r1, r2, r3, stB + sw_off(row, chk));
                    bfr[jp * 2 + 0][0] = r0; bfr[jp * 2 + 0][1] = r1;
                    bfr[jp * 2 + 1][0] = r2; bfr[jp * 2 + 1][1] = r3;
                }
            }
        }
    }

    // ---- epilogue: scale/bias from smem (prefetched), float2 stores ----
    const int tq = lane >> 2;
    const int tr = lane & 3;
    const float* sc_s = (const float*)(smem + SCB_OFF);
    const float* bb_s = (const float*)(smem + SCB_OFF + 512);
#pragma unroll
    for (int j = 0; j < 8; ++j) {
        const int col = wn0 + j * 8 + 2 * tr;        // 0..127 within tile
        const int n = n0 + col;
        const float2 sc = *(const float2*)(sc_s + col);
        const float2 bb = *(const float2*)(bb_s + col);
#pragma unroll
        for (int mi = 0; mi < 2; ++mi) {
            const int mrow = m0 + wm0 + mi * 16 + tq;
            float2 v0, v1;
            v0.x = fmaf(sc.x, acc[mi][j][0], bb.x);
            v0.y = fmaf(sc.y, acc[mi][j][1], bb.y);
            v1.x = fmaf(sc.x, acc[mi][j][2], bb.x);
            v1.y = fmaf(sc.y, acc[mi][j][3], bb.y);
            *(float2*)(out + (size_t)mrow * DOUT + n) = v0;
            *(float2*)(out + (size_t)(mrow + 8) * DOUT + n) = v1;
        }
    }
}

// ============================ launch ========================================
extern "C" void kernel_launch(void* const* d_in, const int* in_sizes, int n_in,
                              void* d_out, int out_size) {
    (void)in_sizes; (void)n_in; (void)out_size;
    const float* x     = (const float*)d_in[0];
    const float* w     = (const float*)d_in[1];
    const float* scale = (const float*)d_in[2];
    const float* b     = (const float*)d_in[3];
    float* out = (float*)d_out;

    prep_fused_kernel<<<PREP_NA + PREP_NB, 256>>>(x, w);

    cudaFuncSetAttribute(qat_gemm_kernel,
                         cudaFuncAttributeMaxDynamicSharedMemorySize,
                         SMEM_TOTAL);
    const int grid = (TOKENS / BM) * (DOUT / BN);   // 8192
    qat_gemm_kernel<<<grid, THREADS, SMEM_TOTAL>>>(scale, b, out);
}

// round 14
// speedup vs baseline: 1.4307x; 1.0032x over previous
#include <cuda_runtime.h>
#include <cuda_fp16.h>
#include <cstdint>

// ============================================================================
// QATLinear: y[t,o] = scale[o] * sum_i x[t,i]*sign(w[o,i]) + b[o]
//
// sign(W)=+-1 exact in fp16; x as fp16, fp32 mma.sync accumulation.
// R14 = R13 GEMM byte-identical (best: 2342us, tensor=80.3%) + prep kernel
// rewritten for DRAM saturation: 2 independent float4 per thread (MLP=2,
// batched loads before stores) + st.global.cs (evict-first) on scratch
// writes. prep was 107us @ 68% DRAM; target ~80us @ ~90%.
// GEMM config: BM=BN=128, BK=64, 8 warps (32x64 tile), STAGES=3, 2 CTAs/SM,
// one barrier/chunk, k-phase stagger, kh-level fragment double buffering,
// smem-prefetched scale/bias epilogue.
// ============================================================================

#define TOKENS 8192
#define DIN    4096
#define DOUT   16384

static constexpr int BM = 128;
static constexpr int BN = 128;
static constexpr int BK = 64;
static constexpr int STAGES = 3;
static constexpr int THREADS = 256;              // 8 warps: 4 (m) x 2 (n)
static constexpr int NCHUNK = DIN / BK;          // 64

static constexpr int A_STAGE_B = BM * BK * 2;    // 16384 B
static constexpr int B_STAGE_B = BN * BK * 2;    // 16384 B
static constexpr int STAGE_B   = A_STAGE_B + B_STAGE_B;   // 32768
static constexpr int SCB_OFF   = STAGES * STAGE_B;        // 98304
static constexpr int SMEM_TOTAL = SCB_OFF + 1024;         // 99328 per CTA

// ---- scratch (device globals: allocation-free rule) ----
__device__ __half g_A [(size_t)TOKENS * DIN];    // 64 MB  (x as fp16)
__device__ __half g_Bs[(size_t)DOUT  * DIN];     // 128 MB (sign(w) as fp16)

// ============================ PTX helpers ===================================
__device__ __forceinline__ uint32_t smem_u32(const void* p) {
    uint32_t a;
    asm("{ .reg .u64 t; cvta.to.shared.u64 t, %1; cvt.u32.u64 %0, t; }"
        : "=r"(a) : "l"(p));
    return a;
}
__device__ __forceinline__ void cp_async16(uint32_t saddr, const void* gptr) {
    asm volatile("cp.async.cg.shared.global [%0], [%1], 16;"
                 :: "r"(saddr), "l"(gptr) : "memory");
}
__device__ __forceinline__ void cp_commit() {
    asm volatile("cp.async.commit_group;" ::: "memory");
}
template <int N>
__device__ __forceinline__ void cp_wait() {
    asm volatile("cp.async.wait_group %0;" :: "n"(N) : "memory");
}
__device__ __forceinline__ void ldmatrix_x4(uint32_t& r0, uint32_t& r1,
                                            uint32_t& r2, uint32_t& r3,
                                            uint32_t addr) {
    asm volatile("ldmatrix.sync.aligned.m8n8.x4.shared.b16 {%0,%1,%2,%3}, [%4];"
                 : "=r"(r0), "=r"(r1), "=r"(r2), "=r"(r3) : "r"(addr));
}
__device__ __forceinline__ void mma_16816(float* c, const uint32_t* a,
                                          const uint32_t* b) {
    asm volatile(
        "mma.sync.aligned.m16n8k16.row.col.f32.f16.f16.f32 "
        "{%0,%1,%2,%3}, {%4,%5,%6,%7}, {%8,%9}, {%0,%1,%2,%3};"
        : "+f"(c[0]), "+f"(c[1]), "+f"(c[2]), "+f"(c[3])
        : "r"(a[0]), "r"(a[1]), "r"(a[2]), "r"(a[3]), "r"(b[0]), "r"(b[1]));
}
__device__ __forceinline__ void stg_cs_v2(void* p, uint2 v) {
    asm volatile("st.global.cs.v2.u32 [%0], {%1, %2};"
                 :: "l"(p), "r"(v.x), "r"(v.y) : "memory");
}
// tile rows: 64 fp16 = 128 B = 8 x 16B chunks; chunk' = chunk ^ (row&7)
__device__ __forceinline__ uint32_t sw_off(int row, int chunk) {
    return (uint32_t)((row << 7) + ((chunk ^ (row & 7)) << 4));
}

// ===================== fused prep kernel (one launch) =======================
// each thread converts TWO independent float4s (MLP=2, loads batched first)
static constexpr size_t A_F4 = (size_t)TOKENS * DIN / 4;   // 8388608
static constexpr size_t B_F4 = (size_t)DOUT  * DIN / 4;    // 16777216
static constexpr unsigned PREP_NA = (unsigned)((A_F4 / 2 + 255) / 256);
static constexpr unsigned PREP_NB = (unsigned)((B_F4 / 2 + 255) / 256);

__device__ __forceinline__ uint2 cvt_a(float4 v) {
    uint32_t h0 = __half_as_ushort(__float2half_rn(v.x))
                | ((uint32_t)__half_as_ushort(__float2half_rn(v.y)) << 16);
    uint32_t h1 = __half_as_ushort(__float2half_rn(v.z))
                | ((uint32_t)__half_as_ushort(__float2half_rn(v.w)) << 16);
    uint2 p; p.x = h0; p.y = h1; return p;
}
__device__ __forceinline__ uint2 cvt_b(float4 v) {
    // sign with 0 -> +1 ; fp16 +1.0 = 0x3C00, -1.0 = 0xBC00
    uint32_t s0 = (v.x >= 0.0f) ? 0x3C00u : 0xBC00u;
    uint32_t s1 = (v.y >= 0.0f) ? 0x3C00u : 0xBC00u;
    uint32_t s2 = (v.z >= 0.0f) ? 0x3C00u : 0xBC00u;
    uint32_t s3 = (v.w >= 0.0f) ? 0x3C00u : 0xBC00u;
    uint2 p; p.x = s0 | (s1 << 16); p.y = s2 | (s3 << 16); return p;
}

__global__ void prep_fused_kernel(const float* __restrict__ x,
                                  const float* __restrict__ w) {
    const unsigned b = blockIdx.x;
    if (b < PREP_NA) {
        const size_t i0 = ((size_t)b * blockDim.x + threadIdx.x) * 2;
        if (i0 + 1 < A_F4) {
            float4 v0 = __ldg((const float4*)x + i0);
            float4 v1 = __ldg((const float4*)x + i0 + 1);
            stg_cs_v2((uint2*)g_A + i0,     cvt_a(v0));
            stg_cs_v2((uint2*)g_A + i0 + 1, cvt_a(v1));
        } else if (i0 < A_F4) {
            stg_cs_v2((uint2*)g_A + i0, cvt_a(__ldg((const float4*)x + i0)));
        }
    } else {
        const size_t i0 = ((size_t)(b - PREP_NA) * blockDim.x + threadIdx.x) * 2;
        if (i0 + 1 < B_F4) {
            float4 v0 = __ldg((const float4*)w + i0);
            float4 v1 = __ldg((const float4*)w + i0 + 1);
            stg_cs_v2((uint2*)g_Bs + i0,     cvt_b(v0));
            stg_cs_v2((uint2*)g_Bs + i0 + 1, cvt_b(v1));
        } else if (i0 < B_F4) {
            stg_cs_v2((uint2*)g_Bs + i0, cvt_b(__ldg((const float4*)w + i0)));
        }
    }
}

// ============================ GEMM kernel ===================================
__global__ void __launch_bounds__(THREADS, 2)
qat_gemm_kernel(const float* __restrict__ scale, const float* __restrict__ bias,
                float* __restrict__ out) {
    extern __shared__ char smem[];
    const uint32_t sbase = smem_u32(smem);
    const int tid  = threadIdx.x;
    const int wid  = tid >> 5;
    const int lane = tid & 31;

    // grouped tile swizzle (GROUP_M = 8): 64 m-tiles x 128 n-tiles
    const int pid   = blockIdx.x;                 // 0 .. 8191
    const int group = pid >> 10;
    const int inb   = pid & 1023;
    const int pid_m = (group << 3) + (inb & 7);
    const int pid_n = inb >> 3;
    const int m0 = pid_m * BM;
    const int n0 = pid_n * BN;

    // phase stagger: wave partners anti-align k-loops
    const int coff = ((pid / 148) & 1) ? (NCHUNK / 2) : 0;

    // warp tile: 32 (m) x 64 (n); warps: 4 (m) x 2 (n)
    const int warp_m = wid & 3;
    const int warp_n = wid >> 2;
    const int wm0 = warp_m * 32;
    const int wn0 = warp_n * 64;

    // ---- global load indices (16B per cp.async; rows are 8x16B chunks) ----
    const int g_row = tid >> 3;               // 0..31
    const int g_chk = tid & 7;

    const __half* gA0 = g_A  + (size_t)(m0 + g_row) * DIN + g_chk * 8;
    const __half* gA1 = gA0 + (size_t)32 * DIN;
    const __half* gA2 = gA0 + (size_t)64 * DIN;
    const __half* gA3 = gA0 + (size_t)96 * DIN;
    const __half* gB0 = g_Bs + (size_t)(n0 + g_row) * DIN + g_chk * 8;
    const __half* gB1 = gB0 + (size_t)32 * DIN;
    const __half* gB2 = gB0 + (size_t)64 * DIN;
    const __half* gB3 = gB0 + (size_t)96 * DIN;

    const uint32_t sO0 = sw_off(g_row,      g_chk);
    const uint32_t sO1 = sw_off(g_row + 32, g_chk);
    const uint32_t sO2 = sw_off(g_row + 64, g_chk);
    const uint32_t sO3 = sw_off(g_row + 96, g_chk);

    auto issue_stage = [&](int cc) {
        const int s = cc % STAGES;
        const int c = (cc + coff) & (NCHUNK - 1);
        const uint32_t stA = sbase + s * STAGE_B;
        const uint32_t stB = stA + A_STAGE_B;
        const size_t kofs = (size_t)c * BK;
        cp_async16(stA + sO0, gA0 + kofs);
        cp_async16(stA + sO1, gA1 + kofs);
        cp_async16(stA + sO2, gA2 + kofs);
        cp_async16(stA + sO3, gA3 + kofs);
        cp_async16(stB + sO0, gB0 + kofs);
        cp_async16(stB + sO1, gB1 + kofs);
        cp_async16(stB + sO2, gB2 + kofs);
        cp_async16(stB + sO3, gB3 + kofs);
    };

    // ---- prologue: scale/bias prefetch bundled with stage 0's group ----
    if (tid < 32)       cp_async16(sbase + SCB_OFF + tid * 16,
                                   scale + n0 + tid * 4);
    else if (tid < 64)  cp_async16(sbase + SCB_OFF + 512 + (tid - 32) * 16,
                                   bias + n0 + (tid - 32) * 4);
    issue_stage(0); cp_commit();
#pragma unroll
    for (int cc = 1; cc < STAGES - 1; ++cc) { issue_stage(cc); cp_commit(); }

    // ---- accumulators: 2 m-frags x 8 n-frags x 4 ----
    float acc[2][8][4];
#pragma unroll
    for (int i = 0; i < 2; ++i)
#pragma unroll
        for (int j = 0; j < 8; ++j)
#pragma unroll
            for (int q = 0; q < 4; ++q) acc[i][j][q] = 0.0f;

    const int lquad = lane >> 3;
    const int lrow  = lane & 7;

#pragma unroll 1
    for (int cc = 0; cc < NCHUNK; ++cc) {
        cp_wait<STAGES - 2>();
        __syncthreads();   // all warps done reading slot cc-1

        const uint32_t stA = sbase + (cc % STAGES) * STAGE_B;
        const uint32_t stB = stA + A_STAGE_B;

        // ---- kh=0 fragment loads FIRST (refill tensor stream immediately) --
        uint32_t afr[2][4];
        uint32_t bfr[8][2];
#pragma unroll
        for (int mi = 0; mi < 2; ++mi) {
            int row = wm0 + mi * 16 + lrow + ((lquad & 1) << 3);
            int chk = (lquad >> 1);
            ldmatrix_x4(afr[mi][0], afr[mi][1], afr[mi][2], afr[mi][3],
                        stA + sw_off(row, chk));
        }
#pragma unroll
        for (int jp = 0; jp < 4; ++jp) {
            int row = wn0 + jp * 16 + lrow + ((lquad >> 1) << 3);
            int chk = (lquad & 1);
            uint32_t r0, r1, r2, r3;
            ldmatrix_x4(r0, r1, r2, r3, stB + sw_off(row, chk));
            bfr[jp * 2 + 0][0] = r0; bfr[jp * 2 + 0][1] = r1;
            bfr[jp * 2 + 1][0] = r2; bfr[jp * 2 + 1][1] = r3;
        }

        // next-stage cp.asyncs AFTER the first fragment batch
        if (cc + STAGES - 1 < NCHUNK) issue_stage(cc + STAGES - 1);
        cp_commit();

#pragma unroll
        for (int kh = 0; kh < 4; ++kh) {      // four k16 halves of BK=64
            // MMAs on current fragments
#pragma unroll
            for (int mi = 0; mi < 2; ++mi)
#pragma unroll
                for (int j = 0; j < 8; ++j)
                    mma_16816(acc[mi][j], afr[mi], bfr[j]);

            // load kh+1 fragments (skipped on last kh)
            if (kh < 3) {
                const int kchunk = (kh + 1) * 2;
#pragma unroll
                for (int mi = 0; mi < 2; ++mi) {
                    int row = wm0 + mi * 16 + lrow + ((lquad & 1) << 3);
                    int chk = kchunk + (lquad >> 1);
                    ldmatrix_x4(afr[mi][0], afr[mi][1], afr[mi][2], afr[mi][3],
                                stA + sw_off(row, chk));
                }
#pragma unroll
                for (int jp = 0; jp < 4; ++jp) {
                    int row = wn0 + jp * 16 + lrow + ((lquad >> 1) << 3);
                    int chk = kchunk + (lquad & 1);
                    uint32_t r0, r1, r2, r3;
                    ldmatrix_x4(r0, r1, r2, r3, stB + sw_off(row, chk));
                    bfr[jp * 2 + 0][0] = r0; bfr[jp * 2 + 0][1] = r1;
                    bfr[jp * 2 + 1][0] = r2; bfr[jp * 2 + 1][1] = r3;
                }
            }
        }
    }

    // ---- epilogue: scale/bias from smem (prefetched), float2 stores ----
    const int tq = lane >> 2;
    const int tr = lane & 3;
    const float* sc_s = (const float*)(smem + SCB_OFF);
    const float* bb_s = (const float*)(smem + SCB_OFF + 512);
#pragma unroll
    for (int j = 0; j < 8; ++j) {
        const int col = wn0 + j * 8 + 2 * tr;        // 0..127 within tile
        const int n = n0 + col;
        const float2 sc = *(const float2*)(sc_s + col);
        const float2 bb = *(const float2*)(bb_s + col);
#pragma unroll
        for (int mi = 0; mi < 2; ++mi) {
            const int mrow = m0 + wm0 + mi * 16 + tq;
            float2 v0, v1;
            v0.x = fmaf(sc.x, acc[mi][j][0], bb.x);
            v0.y = fmaf(sc.y, acc[mi][j][1], bb.y);
            v1.x = fmaf(sc.x, acc[mi][j][2], bb.x);
            v1.y = fmaf(sc.y, acc[mi][j][3], bb.y);
            *(float2*)(out + (size_t)mrow * DOUT + n) = v0;
            *(float2*)(out + (size_t)(mrow + 8) * DOUT + n) = v1;
        }
    }
}

// ============================ launch ========================================
extern "C" void kernel_launch(void* const* d_in, const int* in_sizes, int n_in,
                              void* d_out, int out_size) {
    (void)in_sizes; (void)n_in; (void)out_size;
    const float* x     = (const float*)d_in[0];
    const float* w     = (const float*)d_in[1];
    const float* scale = (const float*)d_in[2];
    const float* b     = (const float*)d_in[3];
    float* out = (float*)d_out;

    prep_fused_kernel<<<PREP_NA + PREP_NB, 256>>>(x, w);

    cudaFuncSetAttribute(qat_gemm_kernel,
                         cudaFuncAttributeMaxDynamicSharedMemorySize,
                         SMEM_TOTAL);
    const int grid = (TOKENS / BM) * (DOUT / BN);   // 8192
    qat_gemm_kernel<<<grid, THREADS, SMEM_TOTAL>>>(scale, b, out);
}

// round 15
// speedup vs baseline: 1.4350x; 1.0030x over previous
#include <cuda_runtime.h>
#include <cuda_fp16.h>
#include <cstdint>

// ============================================================================
// QATLinear: y[t,o] = scale[o] * sum_i x[t,i]*sign(w[o,i]) + b[o]
//
// sign(W)=+-1 exact in fp16; x as fp16, fp32 mma.sync accumulation.
// R15 = GEMM byte-identical to R13/R14 (best; ncu: tensor=80.2%, stable) +
// prep kernel at MLP=4: each thread loads FOUR independent float4s up front
// (hides DRAM+TLB latency per the B300 LDG model), converts, then stores as
// TWO st.global.cs.v4 (16B) -- half the store instructions, aligned sectors.
// Grid sizes divide exactly (A_F4=2^23, B_F4=2^24), no tail branches.
// GEMM config: BM=BN=128, BK=64, 8 warps (32x64 tile), STAGES=3, 2 CTAs/SM,
// one barrier/chunk, k-phase stagger, kh fragment double buffering,
// smem-prefetched scale/bias epilogue.
// ============================================================================

#define TOKENS 8192
#define DIN    4096
#define DOUT   16384

static constexpr int BM = 128;
static constexpr int BN = 128;
static constexpr int BK = 64;
static constexpr int STAGES = 3;
static constexpr int THREADS = 256;              // 8 warps: 4 (m) x 2 (n)
static constexpr int NCHUNK = DIN / BK;          // 64

static constexpr int A_STAGE_B = BM * BK * 2;    // 16384 B
static constexpr int B_STAGE_B = BN * BK * 2;    // 16384 B
static constexpr int STAGE_B   = A_STAGE_B + B_STAGE_B;   // 32768
static constexpr int SCB_OFF   = STAGES * STAGE_B;        // 98304
static constexpr int SMEM_TOTAL = SCB_OFF + 1024;         // 99328 per CTA

// ---- scratch (device globals: allocation-free rule) ----
__device__ __half g_A [(size_t)TOKENS * DIN];    // 64 MB  (x as fp16)
__device__ __half g_Bs[(size_t)DOUT  * DIN];     // 128 MB (sign(w) as fp16)

// ============================ PTX helpers ===================================
__device__ __forceinline__ uint32_t smem_u32(const void* p) {
    uint32_t a;
    asm("{ .reg .u64 t; cvta.to.shared.u64 t, %1; cvt.u32.u64 %0, t; }"
        : "=r"(a) : "l"(p));
    return a;
}
__device__ __forceinline__ void cp_async16(uint32_t saddr, const void* gptr) {
    asm volatile("cp.async.cg.shared.global [%0], [%1], 16;"
                 :: "r"(saddr), "l"(gptr) : "memory");
}
__device__ __forceinline__ void cp_commit() {
    asm volatile("cp.async.commit_group;" ::: "memory");
}
template <int N>
__device__ __forceinline__ void cp_wait() {
    asm volatile("cp.async.wait_group %0;" :: "n"(N) : "memory");
}
__device__ __forceinline__ void ldmatrix_x4(uint32_t& r0, uint32_t& r1,
                                            uint32_t& r2, uint32_t& r3,
                                            uint32_t addr) {
    asm volatile("ldmatrix.sync.aligned.m8n8.x4.shared.b16 {%0,%1,%2,%3}, [%4];"
                 : "=r"(r0), "=r"(r1), "=r"(r2), "=r"(r3) : "r"(addr));
}
__device__ __forceinline__ void mma_16816(float* c, const uint32_t* a,
                                          const uint32_t* b) {
    asm volatile(
        "mma.sync.aligned.m16n8k16.row.col.f32.f16.f16.f32 "
        "{%0,%1,%2,%3}, {%4,%5,%6,%7}, {%8,%9}, {%0,%1,%2,%3};"
        : "+f"(c[0]), "+f"(c[1]), "+f"(c[2]), "+f"(c[3])
        : "r"(a[0]), "r"(a[1]), "r"(a[2]), "r"(a[3]), "r"(b[0]), "r"(b[1]));
}
__device__ __forceinline__ void stg_cs_v4(void* p, uint32_t a, uint32_t b,
                                          uint32_t c, uint32_t d) {
    asm volatile("st.global.cs.v4.u32 [%0], {%1, %2, %3, %4};"
                 :: "l"(p), "r"(a), "r"(b), "r"(c), "r"(d) : "memory");
}
// tile rows: 64 fp16 = 128 B = 8 x 16B chunks; chunk' = chunk ^ (row&7)
__device__ __forceinline__ uint32_t sw_off(int row, int chunk) {
    return (uint32_t)((row << 7) + ((chunk ^ (row & 7)) << 4));
}

// ===================== fused prep kernel (one launch) =======================
// each thread: 4 independent float4 loads (MLP=4) -> 2 x 16B cs stores
static constexpr size_t A_F4 = (size_t)TOKENS * DIN / 4;   // 2^23
static constexpr size_t B_F4 = (size_t)DOUT  * DIN / 4;    // 2^24
static constexpr unsigned PREP_NA = (unsigned)(A_F4 / (4 * 256));  // 8192
static constexpr unsigned PREP_NB = (unsigned)(B_F4 / (4 * 256));  // 16384

__device__ __forceinline__ uint2 cvt_a(float4 v) {
    uint32_t h0 = __half_as_ushort(__float2half_rn(v.x))
                | ((uint32_t)__half_as_ushort(__float2half_rn(v.y)) << 16);
    uint32_t h1 = __half_as_ushort(__float2half_rn(v.z))
                | ((uint32_t)__half_as_ushort(__float2half_rn(v.w)) << 16);
    uint2 p; p.x = h0; p.y = h1; return p;
}
__device__ __forceinline__ uint2 cvt_b(float4 v) {
    // sign with 0 -> +1 ; fp16 +1.0 = 0x3C00, -1.0 = 0xBC00
    uint32_t s0 = (v.x >= 0.0f) ? 0x3C00u : 0xBC00u;
    uint32_t s1 = (v.y >= 0.0f) ? 0x3C00u : 0xBC00u;
    uint32_t s2 = (v.z >= 0.0f) ? 0x3C00u : 0xBC00u;
    uint32_t s3 = (v.w >= 0.0f) ? 0x3C00u : 0xBC00u;
    uint2 p; p.x = s0 | (s1 << 16); p.y = s2 | (s3 << 16); return p;
}

__global__ void prep_fused_kernel(const float* __restrict__ x,
                                  const float* __restrict__ w) {
    const unsigned b = blockIdx.x;
    if (b < PREP_NA) {
        const size_t i0 = ((size_t)b * blockDim.x + threadIdx.x) * 4;
        float4 v0 = __ldg((const float4*)x + i0);
        float4 v1 = __ldg((const float4*)x + i0 + 1);
        float4 v2 = __ldg((const float4*)x + i0 + 2);
        float4 v3 = __ldg((const float4*)x + i0 + 3);
        uint2 p0 = cvt_a(v0), p1 = cvt_a(v1), p2 = cvt_a(v2), p3 = cvt_a(v3);
        stg_cs_v4((uint2*)g_A + i0,     p0.x, p0.y, p1.x, p1.y);
        stg_cs_v4((uint2*)g_A + i0 + 2, p2.x, p2.y, p3.x, p3.y);
    } else {
        const size_t i0 = ((size_t)(b - PREP_NA) * blockDim.x + threadIdx.x) * 4;
        float4 v0 = __ldg((const float4*)w + i0);
        float4 v1 = __ldg((const float4*)w + i0 + 1);
        float4 v2 = __ldg((const float4*)w + i0 + 2);
        float4 v3 = __ldg((const float4*)w + i0 + 3);
        uint2 p0 = cvt_b(v0), p1 = cvt_b(v1), p2 = cvt_b(v2), p3 = cvt_b(v3);
        stg_cs_v4((uint2*)g_Bs + i0,     p0.x, p0.y, p1.x, p1.y);
        stg_cs_v4((uint2*)g_Bs + i0 + 2, p2.x, p2.y, p3.x, p3.y);
    }
}

// ============================ GEMM kernel ===================================
__global__ void __launch_bounds__(THREADS, 2)
qat_gemm_kernel(const float* __restrict__ scale, const float* __restrict__ bias,
                float* __restrict__ out) {
    extern __shared__ char smem[];
    const uint32_t sbase = smem_u32(smem);
    const int tid  = threadIdx.x;
    const int wid  = tid >> 5;
    const int lane = tid & 31;

    // grouped tile swizzle (GROUP_M = 8): 64 m-tiles x 128 n-tiles
    const int pid   = blockIdx.x;                 // 0 .. 8191
    const int group = pid >> 10;
    const int inb   = pid & 1023;
    const int pid_m = (group << 3) + (inb & 7);
    const int pid_n = inb >> 3;
    const int m0 = pid_m * BM;
    const int n0 = pid_n * BN;

    // phase stagger: wave partners anti-align k-loops
    const int coff = ((pid / 148) & 1) ? (NCHUNK / 2) : 0;

    // warp tile: 32 (m) x 64 (n); warps: 4 (m) x 2 (n)
    const int warp_m = wid & 3;
    const int warp_n = wid >> 2;
    const int wm0 = warp_m * 32;
    const int wn0 = warp_n * 64;

    // ---- global load indices (16B per cp.async; rows are 8x16B chunks) ----
    const int g_row = tid >> 3;               // 0..31
    const int g_chk = tid & 7;

    const __half* gA0 = g_A  + (size_t)(m0 + g_row) * DIN + g_chk * 8;
    const __half* gA1 = gA0 + (size_t)32 * DIN;
    const __half* gA2 = gA0 + (size_t)64 * DIN;
    const __half* gA3 = gA0 + (size_t)96 * DIN;
    const __half* gB0 = g_Bs + (size_t)(n0 + g_row) * DIN + g_chk * 8;
    const __half* gB1 = gB0 + (size_t)32 * DIN;
    const __half* gB2 = gB0 + (size_t)64 * DIN;
    const __half* gB3 = gB0 + (size_t)96 * DIN;

    const uint32_t sO0 = sw_off(g_row,      g_chk);
    const uint32_t sO1 = sw_off(g_row + 32, g_chk);
    const uint32_t sO2 = sw_off(g_row + 64, g_chk);
    const uint32_t sO3 = sw_off(g_row + 96, g_chk);

    auto issue_stage = [&](int cc) {
        const int s = cc % STAGES;
        const int c = (cc + coff) & (NCHUNK - 1);
        const uint32_t stA = sbase + s * STAGE_B;
        const uint32_t stB = stA + A_STAGE_B;
        const size_t kofs = (size_t)c * BK;
        cp_async16(stA + sO0, gA0 + kofs);
        cp_async16(stA + sO1, gA1 + kofs);
        cp_async16(stA + sO2, gA2 + kofs);
        cp_async16(stA + sO3, gA3 + kofs);
        cp_async16(stB + sO0, gB0 + kofs);
        cp_async16(stB + sO1, gB1 + kofs);
        cp_async16(stB + sO2, gB2 + kofs);
        cp_async16(stB + sO3, gB3 + kofs);
    };

    // ---- prologue: scale/bias prefetch bundled with stage 0's group ----
    if (tid < 32)       cp_async16(sbase + SCB_OFF + tid * 16,
                                   scale + n0 + tid * 4);
    else if (tid < 64)  cp_async16(sbase + SCB_OFF + 512 + (tid - 32) * 16,
                                   bias + n0 + (tid - 32) * 4);
    issue_stage(0); cp_commit();
#pragma unroll
    for (int cc = 1; cc < STAGES - 1; ++cc) { issue_stage(cc); cp_commit(); }

    // ---- accumulators: 2 m-frags x 8 n-frags x 4 ----
    float acc[2][8][4];
#pragma unroll
    for (int i = 0; i < 2; ++i)
#pragma unroll
        for (int j = 0; j < 8; ++j)
#pragma unroll
            for (int q = 0; q < 4; ++q) acc[i][j][q] = 0.0f;

    const int lquad = lane >> 3;
    const int lrow  = lane & 7;

#pragma unroll 1
    for (int cc = 0; cc < NCHUNK; ++cc) {
        cp_wait<STAGES - 2>();
        __syncthreads();   // all warps done reading slot cc-1

        const uint32_t stA = sbase + (cc % STAGES) * STAGE_B;
        const uint32_t stB = stA + A_STAGE_B;

        // ---- kh=0 fragment loads FIRST (refill tensor stream immediately) --
        uint32_t afr[2][4];
        uint32_t bfr[8][2];
#pragma unroll
        for (int mi = 0; mi < 2; ++mi) {
            int row = wm0 + mi * 16 + lrow + ((lquad & 1) << 3);
            int chk = (lquad >> 1);
            ldmatrix_x4(afr[mi][0], afr[mi][1], afr[mi][2], afr[mi][3],
                        stA + sw_off(row, chk));
        }
#pragma unroll
        for (int jp = 0; jp < 4; ++jp) {
            int row = wn0 + jp * 16 + lrow + ((lquad >> 1) << 3);
            int chk = (lquad & 1);
            uint32_t r0, r1, r2, r3;
            ldmatrix_x4(r0, r1, r2, r3, stB + sw_off(row, chk));
            bfr[jp * 2 + 0][0] = r0; bfr[jp * 2 + 0][1] = r1;
            bfr[jp * 2 + 1][0] = r2; bfr[jp * 2 + 1][1] = r3;
        }

        // next-stage cp.asyncs AFTER the first fragment batch
        if (cc + STAGES - 1 < NCHUNK) issue_stage(cc + STAGES - 1);
        cp_commit();

#pragma unroll
        for (int kh = 0; kh < 4; ++kh) {      // four k16 halves of BK=64
            // MMAs on current fragments
#pragma unroll
            for (int mi = 0; mi < 2; ++mi)
#pragma unroll
                for (int j = 0; j < 8; ++j)
                    mma_16816(acc[mi][j], afr[mi], bfr[j]);

            // load kh+1 fragments (skipped on last kh)
            if (kh < 3) {
                const int kchunk = (kh + 1) * 2;
#pragma unroll
                for (int mi = 0; mi < 2; ++mi) {
                    int row = wm0 + mi * 16 + lrow + ((lquad & 1) << 3);
                    int chk = kchunk + (lquad >> 1);
                    ldmatrix_x4(afr[mi][0], afr[mi][1], afr[mi][2], afr[mi][3],
                                stA + sw_off(row, chk));
                }
#pragma unroll
                for (int jp = 0; jp < 4; ++jp) {
                    int row = wn0 + jp * 16 + lrow + ((lquad >> 1) << 3);
                    int chk = kchunk + (lquad & 1);
                    uint32_t r0, r1, r2, r3;
                    ldmatrix_x4(r0, r1, r2, r3, stB + sw_off(row, chk));
                    bfr[jp * 2 + 0][0] = r0; bfr[jp * 2 + 0][1] = r1;
                    bfr[jp * 2 + 1][0] = r2; bfr[jp * 2 + 1][1] = r3;
                }
            }
        }
    }

    // ---- epilogue: scale/bias from smem (prefetched), float2 stores ----
    const int tq = lane >> 2;
    const int tr = lane & 3;
    const float* sc_s = (const float*)(smem + SCB_OFF);
    const float* bb_s = (const float*)(smem + SCB_OFF + 512);
#pragma unroll
    for (int j = 0; j < 8; ++j) {
        const int col = wn0 + j * 8 + 2 * tr;        // 0..127 within tile
        const int n = n0 + col;
        const float2 sc = *(const float2*)(sc_s + col);
        const float2 bb = *(const float2*)(bb_s + col);
#pragma unroll
        for (int mi = 0; mi < 2; ++mi) {
            const int mrow = m0 + wm0 + mi * 16 + tq;
            float2 v0, v1;
            v0.x = fmaf(sc.x, acc[mi][j][0], bb.x);
            v0.y = fmaf(sc.y, acc[mi][j][1], bb.y);
            v1.x = fmaf(sc.x, acc[mi][j][2], bb.x);
            v1.y = fmaf(sc.y, acc[mi][j][3], bb.y);
            *(float2*)(out + (size_t)mrow * DOUT + n) = v0;
            *(float2*)(out + (size_t)(mrow + 8) * DOUT + n) = v1;
        }
    }
}

// ============================ launch ========================================
extern "C" void kernel_launch(void* const* d_in, const int* in_sizes, int n_in,
                              void* d_out, int out_size) {
    (void)in_sizes; (void)n_in; (void)out_size;
    const float* x     = (const float*)d_in[0];
    const float* w     = (const float*)d_in[1];
    const float* scale = (const float*)d_in[2];
    const float* b     = (const float*)d_in[3];
    float* out = (float*)d_out;

    prep_fused_kernel<<<PREP_NA + PREP_NB, 256>>>(x, w);

    cudaFuncSetAttribute(qat_gemm_kernel,
                         cudaFuncAttributeMaxDynamicSharedMemorySize,
                         SMEM_TOTAL);
    const int grid = (TOKENS / BM) * (DOUT / BN);   // 8192
    qat_gemm_kernel<<<grid, THREADS, SMEM_TOTAL>>>(scale, b, out);
}